// round 12
// baseline (speedup 1.0000x reference)
#include <cuda_runtime.h>
#include <cuda_fp16.h>
#include <cuda_bf16.h>
#include <mma.h>
#include <cstdint>

using namespace nvcuda;

#define FULLMASK 0xffffffffu

// ---------------- problem dims ----------------
#define DMODEL 2048
#define DINNER 2048
#define DXB    512
#define DSTATE 32
#define DTRANK 128
#define DFF    5632
#define NTOK   2048      // BATCH * SEQ
#define SEQLEN 1024
#define PROJ   5248      // 2*DINNER + 2*DXB + DTRANK

// column offsets inside zxbcdt
#define OFF_Z  0
#define OFF_X  2048
#define OFF_B  2560
#define OFF_C  3072
#define OFF_DT 5120

// ---------------- scratch (device globals; no allocation allowed) ----------------
__device__ float  g_zx [(size_t)NTOK * PROJ];
__device__ float  g_dt [(size_t)NTOK * DINNER];
__device__ float  g_ypart[(size_t)128 * 1024 * 128];   // [seq][t][warp*32+p]
__device__ float  g_h  [(size_t)NTOK * DMODEL];
__device__ float  g_gate[(size_t)NTOK * DFF];
__device__ __half g_xn1h [(size_t)NTOK * DMODEL];
__device__ __half g_dtrawh[(size_t)NTOK * DTRANK];
__device__ __half g_ygh [(size_t)NTOK * DINNER];
__device__ __half g_xn2h[(size_t)NTOK * DMODEL];
__device__ __half g_ffh [(size_t)NTOK * DFF];
// fp16 weight staging (one buffer per weight; staged once at launch start)
__device__ __half g_wh_in  [(size_t)PROJ * DMODEL];
__device__ __half g_wh_dt  [(size_t)DINNER * DTRANK];
__device__ __half g_wh_out [(size_t)DMODEL * DINNER];
__device__ __half g_wh_gate[(size_t)DFF * DMODEL];
__device__ __half g_wh_up  [(size_t)DFF * DMODEL];
__device__ __half g_wh_down[(size_t)DMODEL * DFF];

// ---------------- helpers ----------------
__device__ __forceinline__ float softplusf(float x) {
    return (x > 15.f) ? x : log1pf(__expf(x));
}
__device__ __forceinline__ float siluf(float x) {
    return x / (1.f + __expf(-x));
}

__device__ __forceinline__ void cp_async16(void* smem_ptr, const void* gmem_ptr) {
    unsigned saddr = (unsigned)__cvta_generic_to_shared(smem_ptr);
    asm volatile("cp.async.cg.shared.global [%0], [%1], 16;\n" :: "r"(saddr), "l"(gmem_ptr));
}
#define CP_COMMIT()  asm volatile("cp.async.commit_group;\n" ::: "memory")
#define CP_WAIT0()   asm volatile("cp.async.wait_group 0;\n" ::: "memory")
#define CP_WAIT1()   asm volatile("cp.async.wait_group 1;\n" ::: "memory")

// ---------------- weight staging: fp32 -> fp16(RN) ----------------
__global__ void halfw_kernel(const float4* __restrict__ in, __half2* __restrict__ out, int n4)
{
    int i = blockIdx.x * 256 + threadIdx.x;
    if (i < n4) {
        float4 v = in[i];
        out[2 * i]     = __floats2half2_rn(v.x, v.y);
        out[2 * i + 1] = __floats2half2_rn(v.z, v.w);
    }
}

// ---------------- RMSNorm -> fp16 ----------------
__global__ void rmsnorm_kernel(const float* __restrict__ x,
                               const float* __restrict__ w,
                               __half* __restrict__ out)
{
    int t = blockIdx.x;
    const float* xr = x + (size_t)t * DMODEL;
    float s = 0.f;
    const float4* x4 = (const float4*)xr;
    #pragma unroll
    for (int i = threadIdx.x; i < DMODEL / 4; i += 256) {
        float4 v = x4[i];
        s += v.x * v.x + v.y * v.y + v.z * v.z + v.w * v.w;
    }
    #pragma unroll
    for (int o = 16; o; o >>= 1) s += __shfl_xor_sync(FULLMASK, s, o);
    __shared__ float red[8];
    if ((threadIdx.x & 31) == 0) red[threadIdx.x >> 5] = s;
    __syncthreads();
    if (threadIdx.x == 0) {
        float r = 0.f;
        #pragma unroll
        for (int i = 0; i < 8; i++) r += red[i];
        red[0] = rsqrtf(r / (float)DMODEL + 1e-5f);
    }
    __syncthreads();
    float inv = red[0];
    __half* orow = out + (size_t)t * DMODEL;
    for (int i = threadIdx.x; i < DMODEL; i += 256)
        orow[i] = __float2half(xr[i] * inv * w[i]);
}

// ================= GEMM (FP16): C[M,N] = A[M,K]*B[N,K]^T =================
// 128x128 tile, BK=64 halves, 256 thr (8 warps, 2x4), 2-stage cp.async, fp32 accum.
// MODE 2: Cf = acc + extra[m,n]              (out_proj, down)
// MODE 3: Cf = acc                           (gate)
// MODE 4: Ch = half(acc * silu(extra[m,n]))  (up fused)
// MODE 5: Cf = acc; if gn>=OFF_DT also Ch[m,gn-OFF_DT] = half(acc)  (in_proj)
// MODE 6: Cf = softplus(acc + extra[gn])     (dt)
#define HSTRIDE 72
#define HSTAGE  (128 * HSTRIDE)                         // halves per stage per matrix
#define GEMM_SMEM16 (4 * HSTAGE * (int)sizeof(__half))  // 73728 B

template <int MODE>
__global__ __launch_bounds__(256)
void gemm16(const __half* __restrict__ A, int lda,
            const __half* __restrict__ B, int ldb,
            float* __restrict__ Cf, __half* __restrict__ Ch, int ldc,
            const float* __restrict__ extra,
            int K)
{
    extern __shared__ __half hsmem[];
    __half* sA[2] = { hsmem,             hsmem + HSTAGE };
    __half* sB[2] = { hsmem + 2*HSTAGE,  hsmem + 3*HSTAGE };

    const int bm = blockIdx.y * 128;
    const int bn = blockIdx.x * 128;
    const int tid = threadIdx.x;
    const int wid = tid >> 5;
    const int wm = (wid >> 2) * 64;
    const int wn = (wid & 3) * 32;

    wmma::fragment<wmma::accumulator, 16, 16, 16, float> acc[4][2];
    #pragma unroll
    for (int i = 0; i < 4; i++)
        #pragma unroll
        for (int j = 0; j < 2; j++)
            wmma::fill_fragment(acc[i][j], 0.f);

    const int kTiles = K >> 6;

    // loader: 128 rows x 64 halves = 128B/row = 8 chunks of 16B; 1024 chunks/matrix
    auto load_stage = [&](int st, int k0) {
        #pragma unroll
        for (int i = 0; i < 4; i++) {
            int chunk = tid + i * 256;
            int r = chunk >> 3, c = (chunk & 7) << 3;     // c in halves
            cp_async16(sA[st] + r * HSTRIDE + c,
                       A + (size_t)(bm + r) * lda + k0 + c);
            cp_async16(sB[st] + r * HSTRIDE + c,
                       B + (size_t)(bn + r) * ldb + k0 + c);
        }
    };

    load_stage(0, 0);
    CP_COMMIT();

    for (int kt = 0; kt < kTiles; kt++) {
        int st = kt & 1;
        if (kt + 1 < kTiles) {
            load_stage(st ^ 1, (kt + 1) << 6);
            CP_COMMIT();
            CP_WAIT1();
        } else {
            CP_WAIT0();
        }
        __syncthreads();

        #pragma unroll
        for (int kk = 0; kk < 64; kk += 16) {
            wmma::fragment<wmma::matrix_a, 16, 16, 16, __half, wmma::row_major> af[4];
            wmma::fragment<wmma::matrix_b, 16, 16, 16, __half, wmma::col_major> bf[2];
            #pragma unroll
            for (int i = 0; i < 4; i++)
                wmma::load_matrix_sync(af[i], sA[st] + (wm + i * 16) * HSTRIDE + kk, HSTRIDE);
            #pragma unroll
            for (int j = 0; j < 2; j++)
                wmma::load_matrix_sync(bf[j], sB[st] + (wn + j * 16) * HSTRIDE + kk, HSTRIDE);
            #pragma unroll
            for (int i = 0; i < 4; i++)
                #pragma unroll
                for (int j = 0; j < 2; j++)
                    wmma::mma_sync(acc[i][j], af[i], bf[j], acc[i][j]);
        }
        __syncthreads();
    }

    // stage C tile through smem as float (65536 B <= 73728 B)
    float* csm = (float*)hsmem;
    #pragma unroll
    for (int i = 0; i < 4; i++)
        #pragma unroll
        for (int j = 0; j < 2; j++)
            wmma::store_matrix_sync(csm + (wm + i * 16) * 128 + wn + j * 16,
                                    acc[i][j], 128, wmma::mem_row_major);
    __syncthreads();

    #pragma unroll 4
    for (int i = tid; i < 128 * 128; i += 256) {
        int r = i >> 7, c = i & 127;
        float v = csm[i];
        int gm = bm + r, gn = bn + c;
        if (MODE == 2) Cf[(size_t)gm * ldc + gn] = v + extra[(size_t)gm * ldc + gn];
        if (MODE == 3) Cf[(size_t)gm * ldc + gn] = v;
        if (MODE == 4) Ch[(size_t)gm * ldc + gn] =
            __float2half(v * siluf(extra[(size_t)gm * ldc + gn]));
        if (MODE == 5) {
            Cf[(size_t)gm * ldc + gn] = v;
            if (gn >= OFF_DT)
                Ch[(size_t)gm * DTRANK + (gn - OFF_DT)] = __float2half(v);
        }
        if (MODE == 6) Cf[(size_t)gm * ldc + gn] = softplusf(v + extra[gn]);
    }
}

// ---------------- selective scan ----------------
#define PF 8
__global__ __launch_bounds__(128)
void scan_kernel(const float* __restrict__ zx,
                 const float* __restrict__ dtbuf,
                 const float* __restrict__ A_log,
                 float* __restrict__ ypart)
{
    int seq = blockIdx.x;          // 0..127
    int b = seq >> 6;
    int g = seq & 63;
    int w = threadIdx.x >> 5;      // 0..3
    int p = threadIdx.x & 31;      // lane
    int gkv = g >> 2;
    int nbase = w * 8;

    float An[8];
    #pragma unroll
    for (int j = 0; j < 8; j++)
        An[j] = -__expf(A_log[(size_t)(g * 32 + p) * DSTATE + nbase + j]);

    float h[8];
    #pragma unroll
    for (int j = 0; j < 8; j++) h[j] = 0.f;

    const float* dt_base = dtbuf + (size_t)b * SEQLEN * DINNER + g * 32 + p;
    const float* x_base  = zx + (size_t)b * SEQLEN * PROJ + OFF_X + gkv * 32 + p;
    const float* B_base  = zx + (size_t)b * SEQLEN * PROJ + OFF_B + gkv * 32 + p;  // lane = n
    const float* C_base  = zx + (size_t)b * SEQLEN * PROJ + OFF_C + g * 32 + p;    // lane = n
    float* yp = ypart + ((size_t)seq * SEQLEN) * 128 + w * 32 + p;

    float pdt[PF], px[PF], pB[PF], pC[PF];
    #pragma unroll
    for (int i = 0; i < PF; i++) {
        pdt[i] = __ldg(dt_base + (size_t)i * DINNER);
        px[i]  = __ldg(x_base  + (size_t)i * PROJ);
        pB[i]  = __ldg(B_base  + (size_t)i * PROJ);
        pC[i]  = __ldg(C_base  + (size_t)i * PROJ);
    }

    #pragma unroll 8
    for (int t = 0; t < SEQLEN; t++) {
        int slot = t & (PF - 1);
        float dtv = pdt[slot], xv = px[slot], Ball = pB[slot], Call = pC[slot];
        int tn = t + PF;
        if (tn < SEQLEN) {
            pdt[slot] = __ldg(dt_base + (size_t)tn * DINNER);
            px[slot]  = __ldg(x_base  + (size_t)tn * PROJ);
            pB[slot]  = __ldg(B_base  + (size_t)tn * PROJ);
            pC[slot]  = __ldg(C_base  + (size_t)tn * PROJ);
        }
        float dtx = dtv * xv;
        float acc = 0.f;
        #pragma unroll
        for (int j = 0; j < 8; j++) {
            float Bv = __shfl_sync(FULLMASK, Ball, nbase + j);
            float Cv = __shfl_sync(FULLMASK, Call, nbase + j);
            float dA = __expf(dtv * An[j]);
            h[j] = dA * h[j] + dtx * Bv;
            acc += h[j] * Cv;
        }
        yp[(size_t)t * 128] = acc;
    }
}

// ---------------- combine partial y + skip D + silu(z) gate -> half (feeds out_proj) ----------------
__global__ void combine_kernel(const float* __restrict__ ypart,
                               const float* __restrict__ zx,
                               const float* __restrict__ Dp,
                               __half* __restrict__ out)
{
    int idx = blockIdx.x * 256 + threadIdx.x;      // 0 .. NTOK*DINNER
    int tok = idx >> 11;
    int i   = idx & 2047;
    int b = tok >> 10, t = tok & 1023;
    int g = i >> 5, p = i & 31;
    int seq = b * 64 + g;
    int gkv = g >> 2;

    const float* yp = ypart + ((size_t)seq * SEQLEN + t) * 128 + p;
    float y = yp[0] + yp[32] + yp[64] + yp[96];

    float xv = zx[(size_t)tok * PROJ + OFF_X + gkv * 32 + p];
    float zv = zx[(size_t)tok * PROJ + OFF_Z + i];
    y += xv * Dp[i];
    float sig = 1.f / (1.f + __expf(-zv));
    out[(size_t)tok * DINNER + i] = __float2half(y * (zv * sig));
}

// ---------------- launch ----------------
static inline void halfw(const float* w, __half* dst, size_t n)
{
    int n4 = (int)(n / 4);
    halfw_kernel<<<(n4 + 255) / 256, 256>>>((const float4*)w, (__half2*)dst, n4);
}

extern "C" void kernel_launch(void* const* d_in, const int* in_sizes, int n_in,
                              void* d_out, int out_size)
{
    const float* hidden     = (const float*)d_in[0];
    const float* in_proj_w  = (const float*)d_in[1];
    const float* dt_proj_w  = (const float*)d_in[2];
    const float* dt_proj_b  = (const float*)d_in[3];
    const float* A_log      = (const float*)d_in[4];
    const float* D_param    = (const float*)d_in[5];
    const float* out_proj_w = (const float*)d_in[6];
    const float* gate_w     = (const float*)d_in[7];
    const float* up_w       = (const float*)d_in[8];
    const float* down_w     = (const float*)d_in[9];
    const float* norm1_w    = (const float*)d_in[10];
    const float* norm2_w    = (const float*)d_in[11];
    float* out = (float*)d_out;

    float *p_zx, *p_dt, *p_ypart, *p_h, *p_gate;
    __half *p_xn1h, *p_dtrawh, *p_ygh, *p_xn2h, *p_ffh;
    __half *p_win, *p_wdt, *p_wout, *p_wgate, *p_wup, *p_wdown;
    cudaGetSymbolAddress((void**)&p_zx,    g_zx);
    cudaGetSymbolAddress((void**)&p_dt,    g_dt);
    cudaGetSymbolAddress((void**)&p_ypart, g_ypart);
    cudaGetSymbolAddress((void**)&p_h,     g_h);
    cudaGetSymbolAddress((void**)&p_gate,  g_gate);
    cudaGetSymbolAddress((void**)&p_xn1h,  g_xn1h);
    cudaGetSymbolAddress((void**)&p_dtrawh,g_dtrawh);
    cudaGetSymbolAddress((void**)&p_ygh,   g_ygh);
    cudaGetSymbolAddress((void**)&p_xn2h,  g_xn2h);
    cudaGetSymbolAddress((void**)&p_ffh,   g_ffh);
    cudaGetSymbolAddress((void**)&p_win,   g_wh_in);
    cudaGetSymbolAddress((void**)&p_wdt,   g_wh_dt);
    cudaGetSymbolAddress((void**)&p_wout,  g_wh_out);
    cudaGetSymbolAddress((void**)&p_wgate, g_wh_gate);
    cudaGetSymbolAddress((void**)&p_wup,   g_wh_up);
    cudaGetSymbolAddress((void**)&p_wdown, g_wh_down);

    cudaFuncSetAttribute(gemm16<2>, cudaFuncAttributeMaxDynamicSharedMemorySize, GEMM_SMEM16);
    cudaFuncSetAttribute(gemm16<3>, cudaFuncAttributeMaxDynamicSharedMemorySize, GEMM_SMEM16);
    cudaFuncSetAttribute(gemm16<4>, cudaFuncAttributeMaxDynamicSharedMemorySize, GEMM_SMEM16);
    cudaFuncSetAttribute(gemm16<5>, cudaFuncAttributeMaxDynamicSharedMemorySize, GEMM_SMEM16);
    cudaFuncSetAttribute(gemm16<6>, cudaFuncAttributeMaxDynamicSharedMemorySize, GEMM_SMEM16);

    // 0) stage all weights to fp16 once
    halfw(in_proj_w,  p_win,   (size_t)PROJ * DMODEL);
    halfw(dt_proj_w,  p_wdt,   (size_t)DINNER * DTRANK);
    halfw(out_proj_w, p_wout,  (size_t)DMODEL * DINNER);
    halfw(gate_w,     p_wgate, (size_t)DFF * DMODEL);
    halfw(up_w,       p_wup,   (size_t)DFF * DMODEL);
    halfw(down_w,     p_wdown, (size_t)DMODEL * DFF);

    // 1) norm1 -> fp16
    rmsnorm_kernel<<<NTOK, 256>>>(hidden, norm1_w, p_xn1h);
    // 2) in_proj (fp16): zx fp32 + dt_raw fp16 mirror
    gemm16<5><<<dim3(PROJ / 128, NTOK / 128), 256, GEMM_SMEM16>>>(
        p_xn1h, DMODEL, p_win, DMODEL, p_zx, p_dtrawh, PROJ, nullptr, DMODEL);
    // 3) dt (fp16) = softplus(dt_raw @ dt_proj_w^T + b) -> fp32
    gemm16<6><<<dim3(DINNER / 128, NTOK / 128), 256, GEMM_SMEM16>>>(
        p_dtrawh, DTRANK, p_wdt, DTRANK, p_dt, nullptr, DINNER, dt_proj_b, DTRANK);
    // 4) selective scan
    scan_kernel<<<128, 128>>>(p_zx, p_dt, A_log, p_ypart);
    // 5) combine -> ygh (fp16)
    combine_kernel<<<(NTOK * DINNER) / 256, 256>>>(p_ypart, p_zx, D_param, p_ygh);
    // 6) out_proj (fp16) + residual(hidden) -> h (fp32)
    gemm16<2><<<dim3(DMODEL / 128, NTOK / 128), 256, GEMM_SMEM16>>>(
        p_ygh, DINNER, p_wout, DINNER, p_h, nullptr, DMODEL, hidden, DINNER);
    // 7) norm2 -> xn2h (fp16)
    rmsnorm_kernel<<<NTOK, 256>>>(p_h, norm2_w, p_xn2h);
    // 8) gate GEMM (fp16) -> g_gate (fp32)
    gemm16<3><<<dim3(DFF / 128, NTOK / 128), 256, GEMM_SMEM16>>>(
        p_xn2h, DMODEL, p_wgate, DMODEL, p_gate, nullptr, DFF, nullptr, DMODEL);
    // 9) up GEMM (fp16) fused silu(gate)*up -> ffh (fp16)
    gemm16<4><<<dim3(DFF / 128, NTOK / 128), 256, GEMM_SMEM16>>>(
        p_xn2h, DMODEL, p_wup, DMODEL, nullptr, p_ffh, DFF, p_gate, DMODEL);
    // 10) down (fp16) + residual(h) -> out (fp32)
    gemm16<2><<<dim3(DMODEL / 128, NTOK / 128), 256, GEMM_SMEM16>>>(
        p_ffh, DFF, p_wdown, DFF, out, nullptr, DMODEL, p_h, DFF);
}

// round 13
// speedup vs baseline: 1.4736x; 1.4736x over previous
#include <cuda_runtime.h>
#include <cuda_fp16.h>
#include <cuda_bf16.h>
#include <mma.h>
#include <cstdint>

using namespace nvcuda;

#define FULLMASK 0xffffffffu

// ---------------- problem dims ----------------
#define DMODEL 2048
#define DINNER 2048
#define DXB    512
#define DSTATE 32
#define DTRANK 128
#define DFF    5632
#define NTOK   2048      // BATCH * SEQ
#define SEQLEN 1024
#define PROJ   5248      // 2*DINNER + 2*DXB + DTRANK

// column offsets inside zxbcdt
#define OFF_Z  0
#define OFF_X  2048
#define OFF_B  2560
#define OFF_C  3072
#define OFF_DT 5120

// ---------------- scratch (device globals; no allocation allowed) ----------------
__device__ float  g_zx [(size_t)NTOK * PROJ];
__device__ float  g_dt [(size_t)NTOK * DINNER];
__device__ float  g_ypart[(size_t)128 * 1024 * 128];   // [seq][t][warp*32+p]
__device__ float  g_h  [(size_t)NTOK * DMODEL];
__device__ float  g_gate[(size_t)NTOK * DFF];
__device__ __half g_xn1h [(size_t)NTOK * DMODEL];
__device__ __half g_dtrawh[(size_t)NTOK * DTRANK];
__device__ __half g_ygh [(size_t)NTOK * DINNER];
__device__ __half g_xn2h[(size_t)NTOK * DMODEL];
__device__ __half g_ffh [(size_t)NTOK * DFF];
// fp16 weight staging (one buffer per weight; staged once at launch start)
__device__ __half g_wh_in  [(size_t)PROJ * DMODEL];
__device__ __half g_wh_dt  [(size_t)DINNER * DTRANK];
__device__ __half g_wh_out [(size_t)DMODEL * DINNER];
__device__ __half g_wh_gate[(size_t)DFF * DMODEL];
__device__ __half g_wh_up  [(size_t)DFF * DMODEL];
__device__ __half g_wh_down[(size_t)DMODEL * DFF];

// ---------------- helpers ----------------
__device__ __forceinline__ float softplusf(float x) {
    return (x > 15.f) ? x : log1pf(__expf(x));
}
__device__ __forceinline__ float siluf(float x) {
    return x / (1.f + __expf(-x));
}

__device__ __forceinline__ void cp_async16(void* smem_ptr, const void* gmem_ptr) {
    unsigned saddr = (unsigned)__cvta_generic_to_shared(smem_ptr);
    asm volatile("cp.async.cg.shared.global [%0], [%1], 16;\n" :: "r"(saddr), "l"(gmem_ptr));
}
#define CP_COMMIT()  asm volatile("cp.async.commit_group;\n" ::: "memory")
#define CP_WAIT0()   asm volatile("cp.async.wait_group 0;\n" ::: "memory")
#define CP_WAIT1()   asm volatile("cp.async.wait_group 1;\n" ::: "memory")

// ---------------- weight staging: fp32 -> fp16(RN) ----------------
__global__ void halfw_kernel(const float4* __restrict__ in, __half2* __restrict__ out, int n4)
{
    int i = blockIdx.x * 256 + threadIdx.x;
    if (i < n4) {
        float4 v = in[i];
        out[2 * i]     = __floats2half2_rn(v.x, v.y);
        out[2 * i + 1] = __floats2half2_rn(v.z, v.w);
    }
}

// ---------------- slice zx dt_raw columns -> fp16 ----------------
__global__ void cvt_dtraw_kernel(const float* __restrict__ zx, __half* __restrict__ out)
{
    int idx = blockIdx.x * 256 + threadIdx.x;      // 0 .. NTOK*DTRANK
    int tok = idx >> 7;
    int j   = idx & 127;
    out[idx] = __float2half(zx[(size_t)tok * PROJ + OFF_DT + j]);
}

// ---------------- RMSNorm -> fp16 ----------------
__global__ void rmsnorm_kernel(const float* __restrict__ x,
                               const float* __restrict__ w,
                               __half* __restrict__ out)
{
    int t = blockIdx.x;
    const float* xr = x + (size_t)t * DMODEL;
    float s = 0.f;
    const float4* x4 = (const float4*)xr;
    #pragma unroll
    for (int i = threadIdx.x; i < DMODEL / 4; i += 256) {
        float4 v = x4[i];
        s += v.x * v.x + v.y * v.y + v.z * v.z + v.w * v.w;
    }
    #pragma unroll
    for (int o = 16; o; o >>= 1) s += __shfl_xor_sync(FULLMASK, s, o);
    __shared__ float red[8];
    if ((threadIdx.x & 31) == 0) red[threadIdx.x >> 5] = s;
    __syncthreads();
    if (threadIdx.x == 0) {
        float r = 0.f;
        #pragma unroll
        for (int i = 0; i < 8; i++) r += red[i];
        red[0] = rsqrtf(r / (float)DMODEL + 1e-5f);
    }
    __syncthreads();
    float inv = red[0];
    __half* orow = out + (size_t)t * DMODEL;
    for (int i = threadIdx.x; i < DMODEL; i += 256)
        orow[i] = __float2half(xr[i] * inv * w[i]);
}

// ================= GEMM (FP16): C[M,N] = A[M,K]*B[N,K]^T =================
// 128x128 tile, BK=64 halves, 256 thr (8 warps, 2x4), 2-stage cp.async, fp32 accum.
// MODE 2: Cf = acc + extra[m,n]              (out_proj, down)
// MODE 3: Cf = acc                           (gate, in_proj)
// MODE 4: Ch = half(acc * silu(extra[m,n]))  (up fused)
// MODE 6: Cf = softplus(acc + extra[gn])     (dt)
#define HSTRIDE 72
#define HSTAGE  (128 * HSTRIDE)                         // halves per stage per matrix
#define GEMM_SMEM16 (4 * HSTAGE * (int)sizeof(__half))  // 73728 B

template <int MODE>
__global__ __launch_bounds__(256)
void gemm16(const __half* __restrict__ A, int lda,
            const __half* __restrict__ B, int ldb,
            float* __restrict__ Cf, __half* __restrict__ Ch, int ldc,
            const float* __restrict__ extra,
            int K)
{
    extern __shared__ __half hsmem[];
    __half* sA[2] = { hsmem,             hsmem + HSTAGE };
    __half* sB[2] = { hsmem + 2*HSTAGE,  hsmem + 3*HSTAGE };

    const int bm = blockIdx.y * 128;
    const int bn = blockIdx.x * 128;
    const int tid = threadIdx.x;
    const int wid = tid >> 5;
    const int wm = (wid >> 2) * 64;
    const int wn = (wid & 3) * 32;

    wmma::fragment<wmma::accumulator, 16, 16, 16, float> acc[4][2];
    #pragma unroll
    for (int i = 0; i < 4; i++)
        #pragma unroll
        for (int j = 0; j < 2; j++)
            wmma::fill_fragment(acc[i][j], 0.f);

    const int kTiles = K >> 6;

    // loader: 128 rows x 64 halves = 128B/row = 8 chunks of 16B; 1024 chunks/matrix
    auto load_stage = [&](int st, int k0) {
        #pragma unroll
        for (int i = 0; i < 4; i++) {
            int chunk = tid + i * 256;
            int r = chunk >> 3, c = (chunk & 7) << 3;     // c in halves
            cp_async16(sA[st] + r * HSTRIDE + c,
                       A + (size_t)(bm + r) * lda + k0 + c);
            cp_async16(sB[st] + r * HSTRIDE + c,
                       B + (size_t)(bn + r) * ldb + k0 + c);
        }
    };

    load_stage(0, 0);
    CP_COMMIT();

    for (int kt = 0; kt < kTiles; kt++) {
        int st = kt & 1;
        if (kt + 1 < kTiles) {
            load_stage(st ^ 1, (kt + 1) << 6);
            CP_COMMIT();
            CP_WAIT1();
        } else {
            CP_WAIT0();
        }
        __syncthreads();

        #pragma unroll
        for (int kk = 0; kk < 64; kk += 16) {
            wmma::fragment<wmma::matrix_a, 16, 16, 16, __half, wmma::row_major> af[4];
            wmma::fragment<wmma::matrix_b, 16, 16, 16, __half, wmma::col_major> bf[2];
            #pragma unroll
            for (int i = 0; i < 4; i++)
                wmma::load_matrix_sync(af[i], sA[st] + (wm + i * 16) * HSTRIDE + kk, HSTRIDE);
            #pragma unroll
            for (int j = 0; j < 2; j++)
                wmma::load_matrix_sync(bf[j], sB[st] + (wn + j * 16) * HSTRIDE + kk, HSTRIDE);
            #pragma unroll
            for (int i = 0; i < 4; i++)
                #pragma unroll
                for (int j = 0; j < 2; j++)
                    wmma::mma_sync(acc[i][j], af[i], bf[j], acc[i][j]);
        }
        __syncthreads();
    }

    // stage C tile through smem as float (65536 B <= 73728 B)
    float* csm = (float*)hsmem;
    #pragma unroll
    for (int i = 0; i < 4; i++)
        #pragma unroll
        for (int j = 0; j < 2; j++)
            wmma::store_matrix_sync(csm + (wm + i * 16) * 128 + wn + j * 16,
                                    acc[i][j], 128, wmma::mem_row_major);
    __syncthreads();

    #pragma unroll 4
    for (int i = tid; i < 128 * 128; i += 256) {
        int r = i >> 7, c = i & 127;
        float v = csm[i];
        int gm = bm + r, gn = bn + c;
        if (MODE == 2) Cf[(size_t)gm * ldc + gn] = v + extra[(size_t)gm * ldc + gn];
        if (MODE == 3) Cf[(size_t)gm * ldc + gn] = v;
        if (MODE == 4) Ch[(size_t)gm * ldc + gn] =
            __float2half(v * siluf(extra[(size_t)gm * ldc + gn]));
        if (MODE == 6) Cf[(size_t)gm * ldc + gn] = softplusf(v + extra[gn]);
    }
}

// ---------------- selective scan ----------------
#define PF 8
__global__ __launch_bounds__(128)
void scan_kernel(const float* __restrict__ zx,
                 const float* __restrict__ dtbuf,
                 const float* __restrict__ A_log,
                 float* __restrict__ ypart)
{
    int seq = blockIdx.x;          // 0..127
    int b = seq >> 6;
    int g = seq & 63;
    int w = threadIdx.x >> 5;      // 0..3
    int p = threadIdx.x & 31;      // lane
    int gkv = g >> 2;
    int nbase = w * 8;

    float An[8];
    #pragma unroll
    for (int j = 0; j < 8; j++)
        An[j] = -__expf(A_log[(size_t)(g * 32 + p) * DSTATE + nbase + j]);

    float h[8];
    #pragma unroll
    for (int j = 0; j < 8; j++) h[j] = 0.f;

    const float* dt_base = dtbuf + (size_t)b * SEQLEN * DINNER + g * 32 + p;
    const float* x_base  = zx + (size_t)b * SEQLEN * PROJ + OFF_X + gkv * 32 + p;
    const float* B_base  = zx + (size_t)b * SEQLEN * PROJ + OFF_B + gkv * 32 + p;  // lane = n
    const float* C_base  = zx + (size_t)b * SEQLEN * PROJ + OFF_C + g * 32 + p;    // lane = n
    float* yp = ypart + ((size_t)seq * SEQLEN) * 128 + w * 32 + p;

    float pdt[PF], px[PF], pB[PF], pC[PF];
    #pragma unroll
    for (int i = 0; i < PF; i++) {
        pdt[i] = __ldg(dt_base + (size_t)i * DINNER);
        px[i]  = __ldg(x_base  + (size_t)i * PROJ);
        pB[i]  = __ldg(B_base  + (size_t)i * PROJ);
        pC[i]  = __ldg(C_base  + (size_t)i * PROJ);
    }

    #pragma unroll 8
    for (int t = 0; t < SEQLEN; t++) {
        int slot = t & (PF - 1);
        float dtv = pdt[slot], xv = px[slot], Ball = pB[slot], Call = pC[slot];
        int tn = t + PF;
        if (tn < SEQLEN) {
            pdt[slot] = __ldg(dt_base + (size_t)tn * DINNER);
            px[slot]  = __ldg(x_base  + (size_t)tn * PROJ);
            pB[slot]  = __ldg(B_base  + (size_t)tn * PROJ);
            pC[slot]  = __ldg(C_base  + (size_t)tn * PROJ);
        }
        float dtx = dtv * xv;
        float acc = 0.f;
        #pragma unroll
        for (int j = 0; j < 8; j++) {
            float Bv = __shfl_sync(FULLMASK, Ball, nbase + j);
            float Cv = __shfl_sync(FULLMASK, Call, nbase + j);
            float dA = __expf(dtv * An[j]);
            h[j] = dA * h[j] + dtx * Bv;
            acc += h[j] * Cv;
        }
        yp[(size_t)t * 128] = acc;
    }
}

// ---------------- combine partial y + skip D + silu(z) gate -> half (feeds out_proj) ----------------
__global__ void combine_kernel(const float* __restrict__ ypart,
                               const float* __restrict__ zx,
                               const float* __restrict__ Dp,
                               __half* __restrict__ out)
{
    int idx = blockIdx.x * 256 + threadIdx.x;      // 0 .. NTOK*DINNER
    int tok = idx >> 11;
    int i   = idx & 2047;
    int b = tok >> 10, t = tok & 1023;
    int g = i >> 5, p = i & 31;
    int seq = b * 64 + g;
    int gkv = g >> 2;

    const float* yp = ypart + ((size_t)seq * SEQLEN + t) * 128 + p;
    float y = yp[0] + yp[32] + yp[64] + yp[96];

    float xv = zx[(size_t)tok * PROJ + OFF_X + gkv * 32 + p];
    float zv = zx[(size_t)tok * PROJ + OFF_Z + i];
    y += xv * Dp[i];
    float sig = 1.f / (1.f + __expf(-zv));
    out[(size_t)tok * DINNER + i] = __float2half(y * (zv * sig));
}

// ---------------- launch ----------------
static inline void halfw(const float* w, __half* dst, size_t n)
{
    int n4 = (int)(n / 4);
    halfw_kernel<<<(n4 + 255) / 256, 256>>>((const float4*)w, (__half2*)dst, n4);
}

extern "C" void kernel_launch(void* const* d_in, const int* in_sizes, int n_in,
                              void* d_out, int out_size)
{
    const float* hidden     = (const float*)d_in[0];
    const float* in_proj_w  = (const float*)d_in[1];
    const float* dt_proj_w  = (const float*)d_in[2];
    const float* dt_proj_b  = (const float*)d_in[3];
    const float* A_log      = (const float*)d_in[4];
    const float* D_param    = (const float*)d_in[5];
    const float* out_proj_w = (const float*)d_in[6];
    const float* gate_w     = (const float*)d_in[7];
    const float* up_w       = (const float*)d_in[8];
    const float* down_w     = (const float*)d_in[9];
    const float* norm1_w    = (const float*)d_in[10];
    const float* norm2_w    = (const float*)d_in[11];
    float* out = (float*)d_out;

    float *p_zx, *p_dt, *p_ypart, *p_h, *p_gate;
    __half *p_xn1h, *p_dtrawh, *p_ygh, *p_xn2h, *p_ffh;
    __half *p_win, *p_wdt, *p_wout, *p_wgate, *p_wup, *p_wdown;
    cudaGetSymbolAddress((void**)&p_zx,    g_zx);
    cudaGetSymbolAddress((void**)&p_dt,    g_dt);
    cudaGetSymbolAddress((void**)&p_ypart, g_ypart);
    cudaGetSymbolAddress((void**)&p_h,     g_h);
    cudaGetSymbolAddress((void**)&p_gate,  g_gate);
    cudaGetSymbolAddress((void**)&p_xn1h,  g_xn1h);
    cudaGetSymbolAddress((void**)&p_dtrawh,g_dtrawh);
    cudaGetSymbolAddress((void**)&p_ygh,   g_ygh);
    cudaGetSymbolAddress((void**)&p_xn2h,  g_xn2h);
    cudaGetSymbolAddress((void**)&p_ffh,   g_ffh);
    cudaGetSymbolAddress((void**)&p_win,   g_wh_in);
    cudaGetSymbolAddress((void**)&p_wdt,   g_wh_dt);
    cudaGetSymbolAddress((void**)&p_wout,  g_wh_out);
    cudaGetSymbolAddress((void**)&p_wgate, g_wh_gate);
    cudaGetSymbolAddress((void**)&p_wup,   g_wh_up);
    cudaGetSymbolAddress((void**)&p_wdown, g_wh_down);

    cudaFuncSetAttribute(gemm16<2>, cudaFuncAttributeMaxDynamicSharedMemorySize, GEMM_SMEM16);
    cudaFuncSetAttribute(gemm16<3>, cudaFuncAttributeMaxDynamicSharedMemorySize, GEMM_SMEM16);
    cudaFuncSetAttribute(gemm16<4>, cudaFuncAttributeMaxDynamicSharedMemorySize, GEMM_SMEM16);
    cudaFuncSetAttribute(gemm16<6>, cudaFuncAttributeMaxDynamicSharedMemorySize, GEMM_SMEM16);

    // 0) stage all weights to fp16 once
    halfw(in_proj_w,  p_win,   (size_t)PROJ * DMODEL);
    halfw(dt_proj_w,  p_wdt,   (size_t)DINNER * DTRANK);
    halfw(out_proj_w, p_wout,  (size_t)DMODEL * DINNER);
    halfw(gate_w,     p_wgate, (size_t)DFF * DMODEL);
    halfw(up_w,       p_wup,   (size_t)DFF * DMODEL);
    halfw(down_w,     p_wdown, (size_t)DMODEL * DFF);

    // 1) norm1 -> fp16
    rmsnorm_kernel<<<NTOK, 256>>>(hidden, norm1_w, p_xn1h);
    // 2) in_proj (fp16, plain epilogue) -> zx fp32
    gemm16<3><<<dim3(PROJ / 128, NTOK / 128), 256, GEMM_SMEM16>>>(
        p_xn1h, DMODEL, p_win, DMODEL, p_zx, nullptr, PROJ, nullptr, DMODEL);
    // 2b) slice dt_raw columns -> fp16
    cvt_dtraw_kernel<<<(NTOK * DTRANK) / 256, 256>>>(p_zx, p_dtrawh);
    // 3) dt (fp16) = softplus(dt_raw @ dt_proj_w^T + b) -> fp32
    gemm16<6><<<dim3(DINNER / 128, NTOK / 128), 256, GEMM_SMEM16>>>(
        p_dtrawh, DTRANK, p_wdt, DTRANK, p_dt, nullptr, DINNER, dt_proj_b, DTRANK);
    // 4) selective scan
    scan_kernel<<<128, 128>>>(p_zx, p_dt, A_log, p_ypart);
    // 5) combine -> ygh (fp16)
    combine_kernel<<<(NTOK * DINNER) / 256, 256>>>(p_ypart, p_zx, D_param, p_ygh);
    // 6) out_proj (fp16) + residual(hidden) -> h (fp32)
    gemm16<2><<<dim3(DMODEL / 128, NTOK / 128), 256, GEMM_SMEM16>>>(
        p_ygh, DINNER, p_wout, DINNER, p_h, nullptr, DMODEL, hidden, DINNER);
    // 7) norm2 -> xn2h (fp16)
    rmsnorm_kernel<<<NTOK, 256>>>(p_h, norm2_w, p_xn2h);
    // 8) gate GEMM (fp16) -> g_gate (fp32)
    gemm16<3><<<dim3(DFF / 128, NTOK / 128), 256, GEMM_SMEM16>>>(
        p_xn2h, DMODEL, p_wgate, DMODEL, p_gate, nullptr, DFF, nullptr, DMODEL);
    // 9) up GEMM (fp16) fused silu(gate)*up -> ffh (fp16)
    gemm16<4><<<dim3(DFF / 128, NTOK / 128), 256, GEMM_SMEM16>>>(
        p_xn2h, DMODEL, p_wup, DMODEL, nullptr, p_ffh, DFF, p_gate, DMODEL);
    // 10) down (fp16) + residual(h) -> out (fp32)
    gemm16<2><<<dim3(DMODEL / 128, NTOK / 128), 256, GEMM_SMEM16>>>(
        p_ffh, DFF, p_wdown, DFF, out, nullptr, DMODEL, p_h, DFF);
}

// round 14
// speedup vs baseline: 1.4771x; 1.0023x over previous
#include <cuda_runtime.h>
#include <cuda_fp16.h>
#include <cuda_bf16.h>
#include <mma.h>
#include <cstdint>

using namespace nvcuda;

#define FULLMASK 0xffffffffu

// ---------------- problem dims ----------------
#define DMODEL 2048
#define DINNER 2048
#define DXB    512
#define DSTATE 32
#define DTRANK 128
#define DFF    5632
#define NTOK   2048      // BATCH * SEQ
#define SEQLEN 1024
#define PROJ   5248      // 2*DINNER + 2*DXB + DTRANK

// column offsets inside zxbcdt
#define OFF_Z  0
#define OFF_X  2048
#define OFF_B  2560
#define OFF_C  3072
#define OFF_DT 5120

// ---------------- scratch (device globals; no allocation allowed) ----------------
__device__ float  g_zx [(size_t)NTOK * PROJ];
__device__ float  g_dt [(size_t)NTOK * DINNER];
__device__ float  g_ypart[(size_t)128 * 1024 * 256];   // [seq][t][warp*32+p] (8 warps)
__device__ float  g_h  [(size_t)NTOK * DMODEL];
__device__ float  g_gate[(size_t)NTOK * DFF];
__device__ __half g_xn1h [(size_t)NTOK * DMODEL];
__device__ __half g_dtrawh[(size_t)NTOK * DTRANK];
__device__ __half g_ygh [(size_t)NTOK * DINNER];
__device__ __half g_xn2h[(size_t)NTOK * DMODEL];
__device__ __half g_ffh [(size_t)NTOK * DFF];
// fp16 weight staging (one buffer per weight; staged once at launch start)
__device__ __half g_wh_in  [(size_t)PROJ * DMODEL];
__device__ __half g_wh_dt  [(size_t)DINNER * DTRANK];
__device__ __half g_wh_out [(size_t)DMODEL * DINNER];
__device__ __half g_wh_gate[(size_t)DFF * DMODEL];
__device__ __half g_wh_up  [(size_t)DFF * DMODEL];
__device__ __half g_wh_down[(size_t)DMODEL * DFF];

// ---------------- helpers ----------------
__device__ __forceinline__ float softplusf(float x) {
    return (x > 15.f) ? x : log1pf(__expf(x));
}
__device__ __forceinline__ float siluf(float x) {
    return x / (1.f + __expf(-x));
}

__device__ __forceinline__ void cp_async16(void* smem_ptr, const void* gmem_ptr) {
    unsigned saddr = (unsigned)__cvta_generic_to_shared(smem_ptr);
    asm volatile("cp.async.cg.shared.global [%0], [%1], 16;\n" :: "r"(saddr), "l"(gmem_ptr));
}
#define CP_COMMIT()  asm volatile("cp.async.commit_group;\n" ::: "memory")
#define CP_WAIT0()   asm volatile("cp.async.wait_group 0;\n" ::: "memory")
#define CP_WAIT1()   asm volatile("cp.async.wait_group 1;\n" ::: "memory")

// ---------------- weight staging: fp32 -> fp16(RN) ----------------
__global__ void halfw_kernel(const float4* __restrict__ in, __half2* __restrict__ out, int n4)
{
    int i = blockIdx.x * 256 + threadIdx.x;
    if (i < n4) {
        float4 v = in[i];
        out[2 * i]     = __floats2half2_rn(v.x, v.y);
        out[2 * i + 1] = __floats2half2_rn(v.z, v.w);
    }
}

// ---------------- slice zx dt_raw columns -> fp16 ----------------
__global__ void cvt_dtraw_kernel(const float* __restrict__ zx, __half* __restrict__ out)
{
    int idx = blockIdx.x * 256 + threadIdx.x;      // 0 .. NTOK*DTRANK
    int tok = idx >> 7;
    int j   = idx & 127;
    out[idx] = __float2half(zx[(size_t)tok * PROJ + OFF_DT + j]);
}

// ---------------- RMSNorm -> fp16 ----------------
__global__ void rmsnorm_kernel(const float* __restrict__ x,
                               const float* __restrict__ w,
                               __half* __restrict__ out)
{
    int t = blockIdx.x;
    const float* xr = x + (size_t)t * DMODEL;
    float s = 0.f;
    const float4* x4 = (const float4*)xr;
    #pragma unroll
    for (int i = threadIdx.x; i < DMODEL / 4; i += 256) {
        float4 v = x4[i];
        s += v.x * v.x + v.y * v.y + v.z * v.z + v.w * v.w;
    }
    #pragma unroll
    for (int o = 16; o; o >>= 1) s += __shfl_xor_sync(FULLMASK, s, o);
    __shared__ float red[8];
    if ((threadIdx.x & 31) == 0) red[threadIdx.x >> 5] = s;
    __syncthreads();
    if (threadIdx.x == 0) {
        float r = 0.f;
        #pragma unroll
        for (int i = 0; i < 8; i++) r += red[i];
        red[0] = rsqrtf(r / (float)DMODEL + 1e-5f);
    }
    __syncthreads();
    float inv = red[0];
    __half* orow = out + (size_t)t * DMODEL;
    for (int i = threadIdx.x; i < DMODEL; i += 256)
        orow[i] = __float2half(xr[i] * inv * w[i]);
}

// ================= GEMM (FP16): C[M,N] = A[M,K]*B[N,K]^T =================
// 128x128 tile, BK=64 halves, 256 thr (8 warps, 2x4), 2-stage cp.async, fp32 accum.
// MODE 2: Cf = acc + extra[m,n]   (out_proj, down)   [direct fragment epilogue]
// MODE 3: Cf = acc                (gate, in_proj)    [direct fragment epilogue]
// MODE 4: Ch = half(acc * silu(extra[m,n]))  (up fused)       [smem epilogue]
// MODE 6: Cf = softplus(acc + extra[gn])     (dt)             [smem epilogue]
#define HSTRIDE 72
#define HSTAGE  (128 * HSTRIDE)                         // halves per stage per matrix
#define GEMM_SMEM16 (4 * HSTAGE * (int)sizeof(__half))  // 73728 B

template <int MODE>
__global__ __launch_bounds__(256)
void gemm16(const __half* __restrict__ A, int lda,
            const __half* __restrict__ B, int ldb,
            float* __restrict__ Cf, __half* __restrict__ Ch, int ldc,
            const float* __restrict__ extra,
            int K)
{
    extern __shared__ __half hsmem[];
    __half* sA[2] = { hsmem,             hsmem + HSTAGE };
    __half* sB[2] = { hsmem + 2*HSTAGE,  hsmem + 3*HSTAGE };

    const int bm = blockIdx.y * 128;
    const int bn = blockIdx.x * 128;
    const int tid = threadIdx.x;
    const int wid = tid >> 5;
    const int wm = (wid >> 2) * 64;
    const int wn = (wid & 3) * 32;

    wmma::fragment<wmma::accumulator, 16, 16, 16, float> acc[4][2];
    #pragma unroll
    for (int i = 0; i < 4; i++)
        #pragma unroll
        for (int j = 0; j < 2; j++)
            wmma::fill_fragment(acc[i][j], 0.f);

    const int kTiles = K >> 6;

    // loader: 128 rows x 64 halves = 128B/row = 8 chunks of 16B; 1024 chunks/matrix
    auto load_stage = [&](int st, int k0) {
        #pragma unroll
        for (int i = 0; i < 4; i++) {
            int chunk = tid + i * 256;
            int r = chunk >> 3, c = (chunk & 7) << 3;     // c in halves
            cp_async16(sA[st] + r * HSTRIDE + c,
                       A + (size_t)(bm + r) * lda + k0 + c);
            cp_async16(sB[st] + r * HSTRIDE + c,
                       B + (size_t)(bn + r) * ldb + k0 + c);
        }
    };

    load_stage(0, 0);
    CP_COMMIT();

    for (int kt = 0; kt < kTiles; kt++) {
        int st = kt & 1;
        if (kt + 1 < kTiles) {
            load_stage(st ^ 1, (kt + 1) << 6);
            CP_COMMIT();
            CP_WAIT1();
        } else {
            CP_WAIT0();
        }
        __syncthreads();

        #pragma unroll
        for (int kk = 0; kk < 64; kk += 16) {
            wmma::fragment<wmma::matrix_a, 16, 16, 16, __half, wmma::row_major> af[4];
            wmma::fragment<wmma::matrix_b, 16, 16, 16, __half, wmma::col_major> bf[2];
            #pragma unroll
            for (int i = 0; i < 4; i++)
                wmma::load_matrix_sync(af[i], sA[st] + (wm + i * 16) * HSTRIDE + kk, HSTRIDE);
            #pragma unroll
            for (int j = 0; j < 2; j++)
                wmma::load_matrix_sync(bf[j], sB[st] + (wn + j * 16) * HSTRIDE + kk, HSTRIDE);
            #pragma unroll
            for (int i = 0; i < 4; i++)
                #pragma unroll
                for (int j = 0; j < 2; j++)
                    wmma::mma_sync(acc[i][j], af[i], bf[j], acc[i][j]);
        }
        __syncthreads();
    }

    if (MODE == 2 || MODE == 3) {
        // direct fragment -> global epilogue (no smem round trip)
        #pragma unroll
        for (int i = 0; i < 4; i++)
            #pragma unroll
            for (int j = 0; j < 2; j++) {
                float* cptr = Cf + (size_t)(bm + wm + i * 16) * ldc + bn + wn + j * 16;
                if (MODE == 2) {
                    wmma::fragment<wmma::accumulator, 16, 16, 16, float> e;
                    const float* eptr = extra + (size_t)(bm + wm + i * 16) * ldc + bn + wn + j * 16;
                    wmma::load_matrix_sync(e, eptr, ldc, wmma::mem_row_major);
                    #pragma unroll
                    for (int t = 0; t < 8; t++) acc[i][j].x[t] += e.x[t];
                }
                wmma::store_matrix_sync(cptr, acc[i][j], ldc, wmma::mem_row_major);
            }
    } else {
        // stage C tile through smem as float (65536 B <= 73728 B)
        float* csm = (float*)hsmem;
        #pragma unroll
        for (int i = 0; i < 4; i++)
            #pragma unroll
            for (int j = 0; j < 2; j++)
                wmma::store_matrix_sync(csm + (wm + i * 16) * 128 + wn + j * 16,
                                        acc[i][j], 128, wmma::mem_row_major);
        __syncthreads();

        #pragma unroll 4
        for (int i = tid; i < 128 * 128; i += 256) {
            int r = i >> 7, c = i & 127;
            float v = csm[i];
            int gm = bm + r, gn = bn + c;
            if (MODE == 4) Ch[(size_t)gm * ldc + gn] =
                __float2half(v * siluf(extra[(size_t)gm * ldc + gn]));
            if (MODE == 6) Cf[(size_t)gm * ldc + gn] = softplusf(v + extra[gn]);
        }
    }
}

// ---------------- selective scan ----------------
// grid = 128 (b*g), block = 256 (8 warps). lane = p, warp owns 4 n-columns.
// Each warp writes its partial y -> ypart[seq][t][w*32+p]; no intra-block sync.
#define PF 8
__global__ __launch_bounds__(256)
void scan_kernel(const float* __restrict__ zx,
                 const float* __restrict__ dtbuf,
                 const float* __restrict__ A_log,
                 float* __restrict__ ypart)
{
    int seq = blockIdx.x;          // 0..127
    int b = seq >> 6;
    int g = seq & 63;
    int w = threadIdx.x >> 5;      // 0..7
    int p = threadIdx.x & 31;      // lane
    int gkv = g >> 2;
    int nbase = w * 4;

    float An[4];
    #pragma unroll
    for (int j = 0; j < 4; j++)
        An[j] = -__expf(A_log[(size_t)(g * 32 + p) * DSTATE + nbase + j]);

    float h[4];
    #pragma unroll
    for (int j = 0; j < 4; j++) h[j] = 0.f;

    const float* dt_base = dtbuf + (size_t)b * SEQLEN * DINNER + g * 32 + p;
    const float* x_base  = zx + (size_t)b * SEQLEN * PROJ + OFF_X + gkv * 32 + p;
    const float* B_base  = zx + (size_t)b * SEQLEN * PROJ + OFF_B + gkv * 32 + p;  // lane = n
    const float* C_base  = zx + (size_t)b * SEQLEN * PROJ + OFF_C + g * 32 + p;    // lane = n
    float* yp = ypart + ((size_t)seq * SEQLEN) * 256 + w * 32 + p;

    float pdt[PF], px[PF], pB[PF], pC[PF];
    #pragma unroll
    for (int i = 0; i < PF; i++) {
        pdt[i] = __ldg(dt_base + (size_t)i * DINNER);
        px[i]  = __ldg(x_base  + (size_t)i * PROJ);
        pB[i]  = __ldg(B_base  + (size_t)i * PROJ);
        pC[i]  = __ldg(C_base  + (size_t)i * PROJ);
    }

    #pragma unroll 8
    for (int t = 0; t < SEQLEN; t++) {
        int slot = t & (PF - 1);
        float dtv = pdt[slot], xv = px[slot], Ball = pB[slot], Call = pC[slot];
        int tn = t + PF;
        if (tn < SEQLEN) {
            pdt[slot] = __ldg(dt_base + (size_t)tn * DINNER);
            px[slot]  = __ldg(x_base  + (size_t)tn * PROJ);
            pB[slot]  = __ldg(B_base  + (size_t)tn * PROJ);
            pC[slot]  = __ldg(C_base  + (size_t)tn * PROJ);
        }
        float dtx = dtv * xv;
        float acc = 0.f;
        #pragma unroll
        for (int j = 0; j < 4; j++) {
            float Bv = __shfl_sync(FULLMASK, Ball, nbase + j);
            float Cv = __shfl_sync(FULLMASK, Call, nbase + j);
            float dA = __expf(dtv * An[j]);
            h[j] = dA * h[j] + dtx * Bv;
            acc += h[j] * Cv;
        }
        yp[(size_t)t * 256] = acc;
    }
}

// ---------------- combine 8 partial y + skip D + silu(z) gate -> half ----------------
__global__ void combine_kernel(const float* __restrict__ ypart,
                               const float* __restrict__ zx,
                               const float* __restrict__ Dp,
                               __half* __restrict__ out)
{
    int idx = blockIdx.x * 256 + threadIdx.x;      // 0 .. NTOK*DINNER
    int tok = idx >> 11;
    int i   = idx & 2047;
    int b = tok >> 10, t = tok & 1023;
    int g = i >> 5, p = i & 31;
    int seq = b * 64 + g;
    int gkv = g >> 2;

    const float* yp = ypart + ((size_t)seq * SEQLEN + t) * 256 + p;
    float y = 0.f;
    #pragma unroll
    for (int k = 0; k < 8; k++) y += yp[k * 32];

    float xv = zx[(size_t)tok * PROJ + OFF_X + gkv * 32 + p];
    float zv = zx[(size_t)tok * PROJ + OFF_Z + i];
    y += xv * Dp[i];
    float sig = 1.f / (1.f + __expf(-zv));
    out[(size_t)tok * DINNER + i] = __float2half(y * (zv * sig));
}

// ---------------- launch ----------------
static inline void halfw(const float* w, __half* dst, size_t n)
{
    int n4 = (int)(n / 4);
    halfw_kernel<<<(n4 + 255) / 256, 256>>>((const float4*)w, (__half2*)dst, n4);
}

extern "C" void kernel_launch(void* const* d_in, const int* in_sizes, int n_in,
                              void* d_out, int out_size)
{
    const float* hidden     = (const float*)d_in[0];
    const float* in_proj_w  = (const float*)d_in[1];
    const float* dt_proj_w  = (const float*)d_in[2];
    const float* dt_proj_b  = (const float*)d_in[3];
    const float* A_log      = (const float*)d_in[4];
    const float* D_param    = (const float*)d_in[5];
    const float* out_proj_w = (const float*)d_in[6];
    const float* gate_w     = (const float*)d_in[7];
    const float* up_w       = (const float*)d_in[8];
    const float* down_w     = (const float*)d_in[9];
    const float* norm1_w    = (const float*)d_in[10];
    const float* norm2_w    = (const float*)d_in[11];
    float* out = (float*)d_out;

    float *p_zx, *p_dt, *p_ypart, *p_h, *p_gate;
    __half *p_xn1h, *p_dtrawh, *p_ygh, *p_xn2h, *p_ffh;
    __half *p_win, *p_wdt, *p_wout, *p_wgate, *p_wup, *p_wdown;
    cudaGetSymbolAddress((void**)&p_zx,    g_zx);
    cudaGetSymbolAddress((void**)&p_dt,    g_dt);
    cudaGetSymbolAddress((void**)&p_ypart, g_ypart);
    cudaGetSymbolAddress((void**)&p_h,     g_h);
    cudaGetSymbolAddress((void**)&p_gate,  g_gate);
    cudaGetSymbolAddress((void**)&p_xn1h,  g_xn1h);
    cudaGetSymbolAddress((void**)&p_dtrawh,g_dtrawh);
    cudaGetSymbolAddress((void**)&p_ygh,   g_ygh);
    cudaGetSymbolAddress((void**)&p_xn2h,  g_xn2h);
    cudaGetSymbolAddress((void**)&p_ffh,   g_ffh);
    cudaGetSymbolAddress((void**)&p_win,   g_wh_in);
    cudaGetSymbolAddress((void**)&p_wdt,   g_wh_dt);
    cudaGetSymbolAddress((void**)&p_wout,  g_wh_out);
    cudaGetSymbolAddress((void**)&p_wgate, g_wh_gate);
    cudaGetSymbolAddress((void**)&p_wup,   g_wh_up);
    cudaGetSymbolAddress((void**)&p_wdown, g_wh_down);

    cudaFuncSetAttribute(gemm16<2>, cudaFuncAttributeMaxDynamicSharedMemorySize, GEMM_SMEM16);
    cudaFuncSetAttribute(gemm16<3>, cudaFuncAttributeMaxDynamicSharedMemorySize, GEMM_SMEM16);
    cudaFuncSetAttribute(gemm16<4>, cudaFuncAttributeMaxDynamicSharedMemorySize, GEMM_SMEM16);
    cudaFuncSetAttribute(gemm16<6>, cudaFuncAttributeMaxDynamicSharedMemorySize, GEMM_SMEM16);

    // 0) stage all weights to fp16 once
    halfw(in_proj_w,  p_win,   (size_t)PROJ * DMODEL);
    halfw(dt_proj_w,  p_wdt,   (size_t)DINNER * DTRANK);
    halfw(out_proj_w, p_wout,  (size_t)DMODEL * DINNER);
    halfw(gate_w,     p_wgate, (size_t)DFF * DMODEL);
    halfw(up_w,       p_wup,   (size_t)DFF * DMODEL);
    halfw(down_w,     p_wdown, (size_t)DMODEL * DFF);

    // 1) norm1 -> fp16
    rmsnorm_kernel<<<NTOK, 256>>>(hidden, norm1_w, p_xn1h);
    // 2) in_proj (fp16, direct epilogue) -> zx fp32
    gemm16<3><<<dim3(PROJ / 128, NTOK / 128), 256, GEMM_SMEM16>>>(
        p_xn1h, DMODEL, p_win, DMODEL, p_zx, nullptr, PROJ, nullptr, DMODEL);
    // 2b) slice dt_raw columns -> fp16
    cvt_dtraw_kernel<<<(NTOK * DTRANK) / 256, 256>>>(p_zx, p_dtrawh);
    // 3) dt (fp16) = softplus(dt_raw @ dt_proj_w^T + b) -> fp32
    gemm16<6><<<dim3(DINNER / 128, NTOK / 128), 256, GEMM_SMEM16>>>(
        p_dtrawh, DTRANK, p_wdt, DTRANK, p_dt, nullptr, DINNER, dt_proj_b, DTRANK);
    // 4) selective scan (8 warps per sequence)
    scan_kernel<<<128, 256>>>(p_zx, p_dt, A_log, p_ypart);
    // 5) combine -> ygh (fp16)
    combine_kernel<<<(NTOK * DINNER) / 256, 256>>>(p_ypart, p_zx, D_param, p_ygh);
    // 6) out_proj (fp16) + residual(hidden) -> h (fp32)
    gemm16<2><<<dim3(DMODEL / 128, NTOK / 128), 256, GEMM_SMEM16>>>(
        p_ygh, DINNER, p_wout, DINNER, p_h, nullptr, DMODEL, hidden, DINNER);
    // 7) norm2 -> xn2h (fp16)
    rmsnorm_kernel<<<NTOK, 256>>>(p_h, norm2_w, p_xn2h);
    // 8) gate GEMM (fp16) -> g_gate (fp32)
    gemm16<3><<<dim3(DFF / 128, NTOK / 128), 256, GEMM_SMEM16>>>(
        p_xn2h, DMODEL, p_wgate, DMODEL, p_gate, nullptr, DFF, nullptr, DMODEL);
    // 9) up GEMM (fp16) fused silu(gate)*up -> ffh (fp16)
    gemm16<4><<<dim3(DFF / 128, NTOK / 128), 256, GEMM_SMEM16>>>(
        p_xn2h, DMODEL, p_wup, DMODEL, nullptr, p_ffh, DFF, p_gate, DMODEL);
    // 10) down (fp16) + residual(h) -> out (fp32)
    gemm16<2><<<dim3(DMODEL / 128, NTOK / 128), 256, GEMM_SMEM16>>>(
        p_ffh, DFF, p_wdown, DFF, out, nullptr, DMODEL, p_h, DFF);
}

// round 15
// speedup vs baseline: 1.4790x; 1.0013x over previous
#include <cuda_runtime.h>
#include <cuda_fp16.h>
#include <cuda_bf16.h>
#include <mma.h>
#include <cstdint>

using namespace nvcuda;

#define FULLMASK 0xffffffffu

// ---------------- problem dims ----------------
#define DMODEL 2048
#define DINNER 2048
#define DXB    512
#define DSTATE 32
#define DTRANK 128
#define DFF    5632
#define NTOK   2048      // BATCH * SEQ
#define SEQLEN 1024
#define PROJ   5248      // 2*DINNER + 2*DXB + DTRANK

// column offsets inside zxbcdt
#define OFF_Z  0
#define OFF_X  2048
#define OFF_B  2560
#define OFF_C  3072
#define OFF_DT 5120

// scan chunking
#define NCHUNK 8
#define CHUNK  (SEQLEN / NCHUNK)    // 128

// ---------------- scratch (device globals; no allocation allowed) ----------------
__device__ float  g_zx [(size_t)NTOK * PROJ];
__device__ float  g_dt [(size_t)NTOK * DINNER];
__device__ float  g_ypart[(size_t)128 * 1024 * 128];   // [seq][t][w*32+p] (4 warps)
__device__ float  g_hfin[(size_t)128 * NCHUNK * 1024]; // [seq][c][p][n]
__device__ float  g_P   [(size_t)128 * NCHUNK * 1024];
__device__ float  g_hin [(size_t)128 * NCHUNK * 1024];
__device__ float  g_h  [(size_t)NTOK * DMODEL];
__device__ float  g_gate[(size_t)NTOK * DFF];
__device__ __half g_xn1h [(size_t)NTOK * DMODEL];
__device__ __half g_dtrawh[(size_t)NTOK * DTRANK];
__device__ __half g_ygh [(size_t)NTOK * DINNER];
__device__ __half g_xn2h[(size_t)NTOK * DMODEL];
__device__ __half g_ffh [(size_t)NTOK * DFF];
// fp16 weight staging (one buffer per weight; staged once at launch start)
__device__ __half g_wh_in  [(size_t)PROJ * DMODEL];
__device__ __half g_wh_dt  [(size_t)DINNER * DTRANK];
__device__ __half g_wh_out [(size_t)DMODEL * DINNER];
__device__ __half g_wh_gate[(size_t)DFF * DMODEL];
__device__ __half g_wh_up  [(size_t)DFF * DMODEL];
__device__ __half g_wh_down[(size_t)DMODEL * DFF];

// ---------------- helpers ----------------
__device__ __forceinline__ float softplusf(float x) {
    return (x > 15.f) ? x : log1pf(__expf(x));
}
__device__ __forceinline__ float siluf(float x) {
    return x / (1.f + __expf(-x));
}

__device__ __forceinline__ void cp_async16(void* smem_ptr, const void* gmem_ptr) {
    unsigned saddr = (unsigned)__cvta_generic_to_shared(smem_ptr);
    asm volatile("cp.async.cg.shared.global [%0], [%1], 16;\n" :: "r"(saddr), "l"(gmem_ptr));
}
#define CP_COMMIT()  asm volatile("cp.async.commit_group;\n" ::: "memory")
#define CP_WAIT0()   asm volatile("cp.async.wait_group 0;\n" ::: "memory")
#define CP_WAIT1()   asm volatile("cp.async.wait_group 1;\n" ::: "memory")

// ---------------- weight staging: fp32 -> fp16(RN) ----------------
__global__ void halfw_kernel(const float4* __restrict__ in, __half2* __restrict__ out, int n4)
{
    int i = blockIdx.x * 256 + threadIdx.x;
    if (i < n4) {
        float4 v = in[i];
        out[2 * i]     = __floats2half2_rn(v.x, v.y);
        out[2 * i + 1] = __floats2half2_rn(v.z, v.w);
    }
}

// ---------------- slice zx dt_raw columns -> fp16 ----------------
__global__ void cvt_dtraw_kernel(const float* __restrict__ zx, __half* __restrict__ out)
{
    int idx = blockIdx.x * 256 + threadIdx.x;      // 0 .. NTOK*DTRANK
    int tok = idx >> 7;
    int j   = idx & 127;
    out[idx] = __float2half(zx[(size_t)tok * PROJ + OFF_DT + j]);
}

// ---------------- RMSNorm -> fp16 ----------------
__global__ void rmsnorm_kernel(const float* __restrict__ x,
                               const float* __restrict__ w,
                               __half* __restrict__ out)
{
    int t = blockIdx.x;
    const float* xr = x + (size_t)t * DMODEL;
    float s = 0.f;
    const float4* x4 = (const float4*)xr;
    #pragma unroll
    for (int i = threadIdx.x; i < DMODEL / 4; i += 256) {
        float4 v = x4[i];
        s += v.x * v.x + v.y * v.y + v.z * v.z + v.w * v.w;
    }
    #pragma unroll
    for (int o = 16; o; o >>= 1) s += __shfl_xor_sync(FULLMASK, s, o);
    __shared__ float red[8];
    if ((threadIdx.x & 31) == 0) red[threadIdx.x >> 5] = s;
    __syncthreads();
    if (threadIdx.x == 0) {
        float r = 0.f;
        #pragma unroll
        for (int i = 0; i < 8; i++) r += red[i];
        red[0] = rsqrtf(r / (float)DMODEL + 1e-5f);
    }
    __syncthreads();
    float inv = red[0];
    __half* orow = out + (size_t)t * DMODEL;
    for (int i = threadIdx.x; i < DMODEL; i += 256)
        orow[i] = __float2half(xr[i] * inv * w[i]);
}

// ================= GEMM (FP16): C[M,N] = A[M,K]*B[N,K]^T =================
// 128x128 tile, BK=64 halves, 256 thr (8 warps, 2x4), 2-stage cp.async, fp32 accum.
// MODE 2: Cf = acc + extra[m,n]   (out_proj, down)   [direct fragment epilogue]
// MODE 3: Cf = acc                (gate, in_proj)    [direct fragment epilogue]
// MODE 4: Ch = half(acc * silu(extra[m,n]))  (up fused)       [smem epilogue]
// MODE 6: Cf = softplus(acc + extra[gn])     (dt)             [smem epilogue]
#define HSTRIDE 72
#define HSTAGE  (128 * HSTRIDE)                         // halves per stage per matrix
#define GEMM_SMEM16 (4 * HSTAGE * (int)sizeof(__half))  // 73728 B

template <int MODE>
__global__ __launch_bounds__(256)
void gemm16(const __half* __restrict__ A, int lda,
            const __half* __restrict__ B, int ldb,
            float* __restrict__ Cf, __half* __restrict__ Ch, int ldc,
            const float* __restrict__ extra,
            int K)
{
    extern __shared__ __half hsmem[];
    __half* sA[2] = { hsmem,             hsmem + HSTAGE };
    __half* sB[2] = { hsmem + 2*HSTAGE,  hsmem + 3*HSTAGE };

    const int bm = blockIdx.y * 128;
    const int bn = blockIdx.x * 128;
    const int tid = threadIdx.x;
    const int wid = tid >> 5;
    const int wm = (wid >> 2) * 64;
    const int wn = (wid & 3) * 32;

    wmma::fragment<wmma::accumulator, 16, 16, 16, float> acc[4][2];
    #pragma unroll
    for (int i = 0; i < 4; i++)
        #pragma unroll
        for (int j = 0; j < 2; j++)
            wmma::fill_fragment(acc[i][j], 0.f);

    const int kTiles = K >> 6;

    // loader: 128 rows x 64 halves = 128B/row = 8 chunks of 16B; 1024 chunks/matrix
    auto load_stage = [&](int st, int k0) {
        #pragma unroll
        for (int i = 0; i < 4; i++) {
            int chunk = tid + i * 256;
            int r = chunk >> 3, c = (chunk & 7) << 3;     // c in halves
            cp_async16(sA[st] + r * HSTRIDE + c,
                       A + (size_t)(bm + r) * lda + k0 + c);
            cp_async16(sB[st] + r * HSTRIDE + c,
                       B + (size_t)(bn + r) * ldb + k0 + c);
        }
    };

    load_stage(0, 0);
    CP_COMMIT();

    for (int kt = 0; kt < kTiles; kt++) {
        int st = kt & 1;
        if (kt + 1 < kTiles) {
            load_stage(st ^ 1, (kt + 1) << 6);
            CP_COMMIT();
            CP_WAIT1();
        } else {
            CP_WAIT0();
        }
        __syncthreads();

        #pragma unroll
        for (int kk = 0; kk < 64; kk += 16) {
            wmma::fragment<wmma::matrix_a, 16, 16, 16, __half, wmma::row_major> af[4];
            wmma::fragment<wmma::matrix_b, 16, 16, 16, __half, wmma::col_major> bf[2];
            #pragma unroll
            for (int i = 0; i < 4; i++)
                wmma::load_matrix_sync(af[i], sA[st] + (wm + i * 16) * HSTRIDE + kk, HSTRIDE);
            #pragma unroll
            for (int j = 0; j < 2; j++)
                wmma::load_matrix_sync(bf[j], sB[st] + (wn + j * 16) * HSTRIDE + kk, HSTRIDE);
            #pragma unroll
            for (int i = 0; i < 4; i++)
                #pragma unroll
                for (int j = 0; j < 2; j++)
                    wmma::mma_sync(acc[i][j], af[i], bf[j], acc[i][j]);
        }
        __syncthreads();
    }

    if (MODE == 2 || MODE == 3) {
        // direct fragment -> global epilogue (no smem round trip)
        #pragma unroll
        for (int i = 0; i < 4; i++)
            #pragma unroll
            for (int j = 0; j < 2; j++) {
                float* cptr = Cf + (size_t)(bm + wm + i * 16) * ldc + bn + wn + j * 16;
                if (MODE == 2) {
                    wmma::fragment<wmma::accumulator, 16, 16, 16, float> e;
                    const float* eptr = extra + (size_t)(bm + wm + i * 16) * ldc + bn + wn + j * 16;
                    wmma::load_matrix_sync(e, eptr, ldc, wmma::mem_row_major);
                    #pragma unroll
                    for (int t = 0; t < 8; t++) acc[i][j].x[t] += e.x[t];
                }
                wmma::store_matrix_sync(cptr, acc[i][j], ldc, wmma::mem_row_major);
            }
    } else {
        // stage C tile through smem as float (65536 B <= 73728 B)
        float* csm = (float*)hsmem;
        #pragma unroll
        for (int i = 0; i < 4; i++)
            #pragma unroll
            for (int j = 0; j < 2; j++)
                wmma::store_matrix_sync(csm + (wm + i * 16) * 128 + wn + j * 16,
                                        acc[i][j], 128, wmma::mem_row_major);
        __syncthreads();

        #pragma unroll 4
        for (int i = tid; i < 128 * 128; i += 256) {
            int r = i >> 7, c = i & 127;
            float v = csm[i];
            int gm = bm + r, gn = bn + c;
            if (MODE == 4) Ch[(size_t)gm * ldc + gn] =
                __float2half(v * siluf(extra[(size_t)gm * ldc + gn]));
            if (MODE == 6) Cf[(size_t)gm * ldc + gn] = softplusf(v + extra[gn]);
        }
    }
}

// ================= chunked selective scan =================
// Partition: block = (seq, chunk). 4 warps, lane = p, warp owns 8 n-columns.
// h recurrence is linear diagonal: over a chunk, h_end = P ⊙ h_in + h_local.
#define PF 8

// phase 1: chunk-local h and P (chunks 0..NCHUNK-2; last chunk's state unused)
__global__ __launch_bounds__(128)
void scan_p1(const float* __restrict__ zx,
             const float* __restrict__ dtbuf,
             const float* __restrict__ A_log,
             float* __restrict__ hfin, float* __restrict__ Pbuf)
{
    int seq = blockIdx.x;          // 0..127
    int c   = blockIdx.y;          // 0..NCHUNK-2
    int t0  = c * CHUNK;
    int b = seq >> 6;
    int g = seq & 63;
    int w = threadIdx.x >> 5;
    int p = threadIdx.x & 31;
    int gkv = g >> 2;
    int nbase = w * 8;

    float An[8];
    #pragma unroll
    for (int j = 0; j < 8; j++)
        An[j] = -__expf(A_log[(size_t)(g * 32 + p) * DSTATE + nbase + j]);

    float h[8], Pr[8];
    #pragma unroll
    for (int j = 0; j < 8; j++) { h[j] = 0.f; Pr[j] = 1.f; }

    const float* dt_base = dtbuf + ((size_t)b * SEQLEN + t0) * DINNER + g * 32 + p;
    const float* x_base  = zx + ((size_t)b * SEQLEN + t0) * PROJ + OFF_X + gkv * 32 + p;
    const float* B_base  = zx + ((size_t)b * SEQLEN + t0) * PROJ + OFF_B + gkv * 32 + p;

    float pdt[PF], px[PF], pB[PF];
    #pragma unroll
    for (int i = 0; i < PF; i++) {
        pdt[i] = __ldg(dt_base + (size_t)i * DINNER);
        px[i]  = __ldg(x_base  + (size_t)i * PROJ);
        pB[i]  = __ldg(B_base  + (size_t)i * PROJ);
    }

    #pragma unroll 4
    for (int t = 0; t < CHUNK; t++) {
        int slot = t & (PF - 1);
        float dtv = pdt[slot], xv = px[slot], Ball = pB[slot];
        int tn = t + PF;
        if (tn < CHUNK) {
            pdt[slot] = __ldg(dt_base + (size_t)tn * DINNER);
            px[slot]  = __ldg(x_base  + (size_t)tn * PROJ);
            pB[slot]  = __ldg(B_base  + (size_t)tn * PROJ);
        }
        float dtx = dtv * xv;
        #pragma unroll
        for (int j = 0; j < 8; j++) {
            float Bv = __shfl_sync(FULLMASK, Ball, nbase + j);
            float dA = __expf(dtv * An[j]);
            h[j]  = dA * h[j] + dtx * Bv;
            Pr[j] = dA * Pr[j];
        }
    }

    size_t base = (((size_t)seq * NCHUNK + c) * 32 + p) * 32 + nbase;
    #pragma unroll
    for (int j = 0; j < 8; j++) {
        hfin[base + j] = h[j];
        Pbuf[base + j] = Pr[j];
    }
}

// fixup: hin[c] = P[c-1] * hin[c-1] + hfin[c-1]; hin[0] = 0
__global__ void scan_fix(const float* __restrict__ hfin,
                         const float* __restrict__ Pbuf,
                         float* __restrict__ hin)
{
    int id = blockIdx.x * 256 + threadIdx.x;       // 0 .. 128*1024
    int seq = id >> 10;
    int pn  = id & 1023;
    size_t base = (size_t)seq * NCHUNK * 1024 + pn;
    float hc = 0.f;
    hin[base] = 0.f;
    #pragma unroll
    for (int c = 1; c < NCHUNK; c++) {
        size_t prev = base + (size_t)(c - 1) * 1024;
        hc = Pbuf[prev] * hc + hfin[prev];
        hin[base + (size_t)c * 1024] = hc;
    }
}

// phase 2: full scan per chunk with correct h_in, emitting y partials
__global__ __launch_bounds__(128)
void scan_p2(const float* __restrict__ zx,
             const float* __restrict__ dtbuf,
             const float* __restrict__ A_log,
             const float* __restrict__ hin,
             float* __restrict__ ypart)
{
    int seq = blockIdx.x;          // 0..127
    int c   = blockIdx.y;          // 0..NCHUNK-1
    int t0  = c * CHUNK;
    int b = seq >> 6;
    int g = seq & 63;
    int w = threadIdx.x >> 5;
    int p = threadIdx.x & 31;
    int gkv = g >> 2;
    int nbase = w * 8;

    float An[8];
    #pragma unroll
    for (int j = 0; j < 8; j++)
        An[j] = -__expf(A_log[(size_t)(g * 32 + p) * DSTATE + nbase + j]);

    float h[8];
    {
        size_t base = (((size_t)seq * NCHUNK + c) * 32 + p) * 32 + nbase;
        #pragma unroll
        for (int j = 0; j < 8; j++) h[j] = hin[base + j];
    }

    const float* dt_base = dtbuf + ((size_t)b * SEQLEN + t0) * DINNER + g * 32 + p;
    const float* x_base  = zx + ((size_t)b * SEQLEN + t0) * PROJ + OFF_X + gkv * 32 + p;
    const float* B_base  = zx + ((size_t)b * SEQLEN + t0) * PROJ + OFF_B + gkv * 32 + p;
    const float* C_base  = zx + ((size_t)b * SEQLEN + t0) * PROJ + OFF_C + g * 32 + p;
    float* yp = ypart + ((size_t)seq * SEQLEN + t0) * 128 + w * 32 + p;

    float pdt[PF], px[PF], pB[PF], pC[PF];
    #pragma unroll
    for (int i = 0; i < PF; i++) {
        pdt[i] = __ldg(dt_base + (size_t)i * DINNER);
        px[i]  = __ldg(x_base  + (size_t)i * PROJ);
        pB[i]  = __ldg(B_base  + (size_t)i * PROJ);
        pC[i]  = __ldg(C_base  + (size_t)i * PROJ);
    }

    #pragma unroll 4
    for (int t = 0; t < CHUNK; t++) {
        int slot = t & (PF - 1);
        float dtv = pdt[slot], xv = px[slot], Ball = pB[slot], Call = pC[slot];
        int tn = t + PF;
        if (tn < CHUNK) {
            pdt[slot] = __ldg(dt_base + (size_t)tn * DINNER);
            px[slot]  = __ldg(x_base  + (size_t)tn * PROJ);
            pB[slot]  = __ldg(B_base  + (size_t)tn * PROJ);
            pC[slot]  = __ldg(C_base  + (size_t)tn * PROJ);
        }
        float dtx = dtv * xv;
        float acc = 0.f;
        #pragma unroll
        for (int j = 0; j < 8; j++) {
            float Bv = __shfl_sync(FULLMASK, Ball, nbase + j);
            float Cv = __shfl_sync(FULLMASK, Call, nbase + j);
            float dA = __expf(dtv * An[j]);
            h[j] = dA * h[j] + dtx * Bv;
            acc += h[j] * Cv;
        }
        yp[(size_t)t * 128] = acc;
    }
}

// ---------------- combine 4 partial y + skip D + silu(z) gate -> half ----------------
__global__ void combine_kernel(const float* __restrict__ ypart,
                               const float* __restrict__ zx,
                               const float* __restrict__ Dp,
                               __half* __restrict__ out)
{
    int idx = blockIdx.x * 256 + threadIdx.x;      // 0 .. NTOK*DINNER
    int tok = idx >> 11;
    int i   = idx & 2047;
    int b = tok >> 10, t = tok & 1023;
    int g = i >> 5, p = i & 31;
    int seq = b * 64 + g;
    int gkv = g >> 2;

    const float* yp = ypart + ((size_t)seq * SEQLEN + t) * 128 + p;
    float y = yp[0] + yp[32] + yp[64] + yp[96];

    float xv = zx[(size_t)tok * PROJ + OFF_X + gkv * 32 + p];
    float zv = zx[(size_t)tok * PROJ + OFF_Z + i];
    y += xv * Dp[i];
    float sig = 1.f / (1.f + __expf(-zv));
    out[(size_t)tok * DINNER + i] = __float2half(y * (zv * sig));
}

// ---------------- launch ----------------
static inline void halfw(const float* w, __half* dst, size_t n)
{
    int n4 = (int)(n / 4);
    halfw_kernel<<<(n4 + 255) / 256, 256>>>((const float4*)w, (__half2*)dst, n4);
}

extern "C" void kernel_launch(void* const* d_in, const int* in_sizes, int n_in,
                              void* d_out, int out_size)
{
    const float* hidden     = (const float*)d_in[0];
    const float* in_proj_w  = (const float*)d_in[1];
    const float* dt_proj_w  = (const float*)d_in[2];
    const float* dt_proj_b  = (const float*)d_in[3];
    const float* A_log      = (const float*)d_in[4];
    const float* D_param    = (const float*)d_in[5];
    const float* out_proj_w = (const float*)d_in[6];
    const float* gate_w     = (const float*)d_in[7];
    const float* up_w       = (const float*)d_in[8];
    const float* down_w     = (const float*)d_in[9];
    const float* norm1_w    = (const float*)d_in[10];
    const float* norm2_w    = (const float*)d_in[11];
    float* out = (float*)d_out;

    float *p_zx, *p_dt, *p_ypart, *p_hfin, *p_P, *p_hin, *p_h, *p_gate;
    __half *p_xn1h, *p_dtrawh, *p_ygh, *p_xn2h, *p_ffh;
    __half *p_win, *p_wdt, *p_wout, *p_wgate, *p_wup, *p_wdown;
    cudaGetSymbolAddress((void**)&p_zx,    g_zx);
    cudaGetSymbolAddress((void**)&p_dt,    g_dt);
    cudaGetSymbolAddress((void**)&p_ypart, g_ypart);
    cudaGetSymbolAddress((void**)&p_hfin,  g_hfin);
    cudaGetSymbolAddress((void**)&p_P,     g_P);
    cudaGetSymbolAddress((void**)&p_hin,   g_hin);
    cudaGetSymbolAddress((void**)&p_h,     g_h);
    cudaGetSymbolAddress((void**)&p_gate,  g_gate);
    cudaGetSymbolAddress((void**)&p_xn1h,  g_xn1h);
    cudaGetSymbolAddress((void**)&p_dtrawh,g_dtrawh);
    cudaGetSymbolAddress((void**)&p_ygh,   g_ygh);
    cudaGetSymbolAddress((void**)&p_xn2h,  g_xn2h);
    cudaGetSymbolAddress((void**)&p_ffh,   g_ffh);
    cudaGetSymbolAddress((void**)&p_win,   g_wh_in);
    cudaGetSymbolAddress((void**)&p_wdt,   g_wh_dt);
    cudaGetSymbolAddress((void**)&p_wout,  g_wh_out);
    cudaGetSymbolAddress((void**)&p_wgate, g_wh_gate);
    cudaGetSymbolAddress((void**)&p_wup,   g_wh_up);
    cudaGetSymbolAddress((void**)&p_wdown, g_wh_down);

    cudaFuncSetAttribute(gemm16<2>, cudaFuncAttributeMaxDynamicSharedMemorySize, GEMM_SMEM16);
    cudaFuncSetAttribute(gemm16<3>, cudaFuncAttributeMaxDynamicSharedMemorySize, GEMM_SMEM16);
    cudaFuncSetAttribute(gemm16<4>, cudaFuncAttributeMaxDynamicSharedMemorySize, GEMM_SMEM16);
    cudaFuncSetAttribute(gemm16<6>, cudaFuncAttributeMaxDynamicSharedMemorySize, GEMM_SMEM16);

    // 0) stage all weights to fp16 once
    halfw(in_proj_w,  p_win,   (size_t)PROJ * DMODEL);
    halfw(dt_proj_w,  p_wdt,   (size_t)DINNER * DTRANK);
    halfw(out_proj_w, p_wout,  (size_t)DMODEL * DINNER);
    halfw(gate_w,     p_wgate, (size_t)DFF * DMODEL);
    halfw(up_w,       p_wup,   (size_t)DFF * DMODEL);
    halfw(down_w,     p_wdown, (size_t)DMODEL * DFF);

    // 1) norm1 -> fp16
    rmsnorm_kernel<<<NTOK, 256>>>(hidden, norm1_w, p_xn1h);
    // 2) in_proj (fp16) -> zx fp32
    gemm16<3><<<dim3(PROJ / 128, NTOK / 128), 256, GEMM_SMEM16>>>(
        p_xn1h, DMODEL, p_win, DMODEL, p_zx, nullptr, PROJ, nullptr, DMODEL);
    // 2b) slice dt_raw columns -> fp16
    cvt_dtraw_kernel<<<(NTOK * DTRANK) / 256, 256>>>(p_zx, p_dtrawh);
    // 3) dt (fp16) = softplus(dt_raw @ dt_proj_w^T + b) -> fp32
    gemm16<6><<<dim3(DINNER / 128, NTOK / 128), 256, GEMM_SMEM16>>>(
        p_dtrawh, DTRANK, p_wdt, DTRANK, p_dt, nullptr, DINNER, dt_proj_b, DTRANK);
    // 4) chunked selective scan
    scan_p1<<<dim3(128, NCHUNK - 1), 128>>>(p_zx, p_dt, A_log, p_hfin, p_P);
    scan_fix<<<(128 * 1024) / 256, 256>>>(p_hfin, p_P, p_hin);
    scan_p2<<<dim3(128, NCHUNK), 128>>>(p_zx, p_dt, A_log, p_hin, p_ypart);
    // 5) combine -> ygh (fp16)
    combine_kernel<<<(NTOK * DINNER) / 256, 256>>>(p_ypart, p_zx, D_param, p_ygh);
    // 6) out_proj (fp16) + residual(hidden) -> h (fp32)
    gemm16<2><<<dim3(DMODEL / 128, NTOK / 128), 256, GEMM_SMEM16>>>(
        p_ygh, DINNER, p_wout, DINNER, p_h, nullptr, DMODEL, hidden, DINNER);
    // 7) norm2 -> xn2h (fp16)
    rmsnorm_kernel<<<NTOK, 256>>>(p_h, norm2_w, p_xn2h);
    // 8) gate GEMM (fp16) -> g_gate (fp32)
    gemm16<3><<<dim3(DFF / 128, NTOK / 128), 256, GEMM_SMEM16>>>(
        p_xn2h, DMODEL, p_wgate, DMODEL, p_gate, nullptr, DFF, nullptr, DMODEL);
    // 9) up GEMM (fp16) fused silu(gate)*up -> ffh (fp16)
    gemm16<4><<<dim3(DFF / 128, NTOK / 128), 256, GEMM_SMEM16>>>(
        p_xn2h, DMODEL, p_wup, DMODEL, nullptr, p_ffh, DFF, p_gate, DMODEL);
    // 10) down (fp16) + residual(h) -> out (fp32)
    gemm16<2><<<dim3(DMODEL / 128, NTOK / 128), 256, GEMM_SMEM16>>>(
        p_ffh, DFF, p_wdown, DFF, out, nullptr, DMODEL, p_h, DFF);
}

// round 16
// speedup vs baseline: 1.5832x; 1.0704x over previous
#include <cuda_runtime.h>
#include <cuda_fp16.h>
#include <cuda_bf16.h>
#include <mma.h>
#include <cstdint>

using namespace nvcuda;

#define FULLMASK 0xffffffffu

// ---------------- problem dims ----------------
#define DMODEL 2048
#define DINNER 2048
#define DXB    512
#define DSTATE 32
#define DTRANK 128
#define DFF    5632
#define NTOK   2048      // BATCH * SEQ
#define SEQLEN 1024
#define PROJ   5248      // 2*DINNER + 2*DXB + DTRANK

// column offsets inside zxbcdt
#define OFF_Z  0
#define OFF_X  2048
#define OFF_B  2560
#define OFF_C  3072
#define OFF_DT 5120

// scan chunking
#define NCHUNK 8
#define CHUNK  (SEQLEN / NCHUNK)    // 128

// ---------------- scratch (device globals; no allocation allowed) ----------------
__device__ float  g_zx [(size_t)NTOK * PROJ];
__device__ float  g_dt [(size_t)NTOK * DINNER];
__device__ float  g_ypart[(size_t)128 * 1024 * 128];   // [seq][t][w*32+p] (4 warps)
__device__ float  g_hfin[(size_t)128 * NCHUNK * 1024]; // [seq][c][p][n]
__device__ float  g_P   [(size_t)128 * NCHUNK * 1024];
__device__ float  g_hin [(size_t)128 * NCHUNK * 1024];
__device__ float  g_h  [(size_t)NTOK * DMODEL];
__device__ float  g_gate[(size_t)NTOK * DFF];
__device__ __half g_xn1h [(size_t)NTOK * DMODEL];
__device__ __half g_dtrawh[(size_t)NTOK * DTRANK];
__device__ __half g_ygh [(size_t)NTOK * DINNER];
__device__ __half g_xn2h[(size_t)NTOK * DMODEL];
__device__ __half g_ffh [(size_t)NTOK * DFF];
// fp16 weight staging (one buffer per weight; staged once at launch start)
__device__ __half g_wh_in  [(size_t)PROJ * DMODEL];
__device__ __half g_wh_dt  [(size_t)DINNER * DTRANK];
__device__ __half g_wh_out [(size_t)DMODEL * DINNER];
__device__ __half g_wh_gate[(size_t)DFF * DMODEL];
__device__ __half g_wh_up  [(size_t)DFF * DMODEL];
__device__ __half g_wh_down[(size_t)DMODEL * DFF];

// ---------------- helpers ----------------
__device__ __forceinline__ float softplusf(float x) {
    return (x > 15.f) ? x : log1pf(__expf(x));
}
__device__ __forceinline__ float siluf(float x) {
    return x / (1.f + __expf(-x));
}

__device__ __forceinline__ void cp_async16(void* smem_ptr, const void* gmem_ptr) {
    unsigned saddr = (unsigned)__cvta_generic_to_shared(smem_ptr);
    asm volatile("cp.async.cg.shared.global [%0], [%1], 16;\n" :: "r"(saddr), "l"(gmem_ptr));
}
#define CP_COMMIT()  asm volatile("cp.async.commit_group;\n" ::: "memory")
#define CP_WAIT0()   asm volatile("cp.async.wait_group 0;\n" ::: "memory")
#define CP_WAIT1()   asm volatile("cp.async.wait_group 1;\n" ::: "memory")

// ---------------- weight staging: fp32 -> fp16(RN) ----------------
__global__ void halfw_kernel(const float4* __restrict__ in, __half2* __restrict__ out, int n4)
{
    int i = blockIdx.x * 256 + threadIdx.x;
    if (i < n4) {
        float4 v = in[i];
        out[2 * i]     = __floats2half2_rn(v.x, v.y);
        out[2 * i + 1] = __floats2half2_rn(v.z, v.w);
    }
}

// ---------------- slice zx dt_raw columns -> fp16 ----------------
__global__ void cvt_dtraw_kernel(const float* __restrict__ zx, __half* __restrict__ out)
{
    int idx = blockIdx.x * 256 + threadIdx.x;      // 0 .. NTOK*DTRANK
    int tok = idx >> 7;
    int j   = idx & 127;
    out[idx] = __float2half(zx[(size_t)tok * PROJ + OFF_DT + j]);
}

// ---------------- RMSNorm -> fp16 ----------------
__global__ void rmsnorm_kernel(const float* __restrict__ x,
                               const float* __restrict__ w,
                               __half* __restrict__ out)
{
    int t = blockIdx.x;
    const float* xr = x + (size_t)t * DMODEL;
    float s = 0.f;
    const float4* x4 = (const float4*)xr;
    #pragma unroll
    for (int i = threadIdx.x; i < DMODEL / 4; i += 256) {
        float4 v = x4[i];
        s += v.x * v.x + v.y * v.y + v.z * v.z + v.w * v.w;
    }
    #pragma unroll
    for (int o = 16; o; o >>= 1) s += __shfl_xor_sync(FULLMASK, s, o);
    __shared__ float red[8];
    if ((threadIdx.x & 31) == 0) red[threadIdx.x >> 5] = s;
    __syncthreads();
    if (threadIdx.x == 0) {
        float r = 0.f;
        #pragma unroll
        for (int i = 0; i < 8; i++) r += red[i];
        red[0] = rsqrtf(r / (float)DMODEL + 1e-5f);
    }
    __syncthreads();
    float inv = red[0];
    __half* orow = out + (size_t)t * DMODEL;
    for (int i = threadIdx.x; i < DMODEL; i += 256)
        orow[i] = __float2half(xr[i] * inv * w[i]);
}

// ================= GEMM (FP16): C[M,N] = A[M,K]*B[N,K]^T =================
// 128x128 tile, BK=64 halves, 256 thr (8 warps, 2x4), 3-stage cp.async pipeline
// with ONE __syncthreads per K-tile, fp32 accumulate.
// MODE 2: Cf = acc + extra[m,n]   (out_proj, down)   [direct fragment epilogue]
// MODE 3: Cf = acc                (gate, in_proj)    [direct fragment epilogue]
// MODE 4: Ch = half(acc * silu(extra[m,n]))  (up fused)       [smem epilogue]
// MODE 6: Cf = softplus(acc + extra[gn])     (dt)             [smem epilogue]
#define HSTRIDE 72
#define HSTAGE  (128 * HSTRIDE)                         // halves per stage per matrix
#define NST     3
#define GEMM_SMEM16 (2 * NST * HSTAGE * (int)sizeof(__half))  // 110592 B

template <int MODE>
__global__ __launch_bounds__(256)
void gemm16(const __half* __restrict__ A, int lda,
            const __half* __restrict__ B, int ldb,
            float* __restrict__ Cf, __half* __restrict__ Ch, int ldc,
            const float* __restrict__ extra,
            int K)
{
    extern __shared__ __half hsmem[];
    __half* sA[NST] = { hsmem,              hsmem + 2*HSTAGE, hsmem + 4*HSTAGE };
    __half* sB[NST] = { hsmem + HSTAGE,     hsmem + 3*HSTAGE, hsmem + 5*HSTAGE };

    const int bm = blockIdx.y * 128;
    const int bn = blockIdx.x * 128;
    const int tid = threadIdx.x;
    const int wid = tid >> 5;
    const int wm = (wid >> 2) * 64;
    const int wn = (wid & 3) * 32;

    wmma::fragment<wmma::accumulator, 16, 16, 16, float> acc[4][2];
    #pragma unroll
    for (int i = 0; i < 4; i++)
        #pragma unroll
        for (int j = 0; j < 2; j++)
            wmma::fill_fragment(acc[i][j], 0.f);

    const int kTiles = K >> 6;

    // loader: 128 rows x 64 halves = 128B/row = 8 chunks of 16B; 1024 chunks/matrix
    auto load_stage = [&](int st, int k0) {
        #pragma unroll
        for (int i = 0; i < 4; i++) {
            int chunk = tid + i * 256;
            int r = chunk >> 3, c = (chunk & 7) << 3;     // c in halves
            cp_async16(sA[st] + r * HSTRIDE + c,
                       A + (size_t)(bm + r) * lda + k0 + c);
            cp_async16(sB[st] + r * HSTRIDE + c,
                       B + (size_t)(bn + r) * ldb + k0 + c);
        }
    };

    // prologue: stages 0 and 1 in flight (one commit group each)
    load_stage(0, 0);
    CP_COMMIT();
    if (kTiles > 1) { load_stage(1, 64); }
    CP_COMMIT();     // empty group when kTiles==1 keeps accounting uniform

    for (int kt = 0; kt < kTiles; kt++) {
        // retire tile kt's group (outstanding: kt, kt+1 if it exists)
        if (kt + 1 < kTiles) { CP_WAIT1(); } else { CP_WAIT0(); }
        // single barrier: (a) tile kt data visible to all warps,
        // (b) all warps done computing tile kt-1, whose buffer ((kt-1)%3
        //     == (kt+2)%3) the prefetch below overwrites.
        __syncthreads();
        if (kt + 2 < kTiles) {
            load_stage((kt + 2) % NST, (kt + 2) << 6);
            CP_COMMIT();
        }

        int st = kt % NST;
        #pragma unroll
        for (int kk = 0; kk < 64; kk += 16) {
            wmma::fragment<wmma::matrix_a, 16, 16, 16, __half, wmma::row_major> af[4];
            wmma::fragment<wmma::matrix_b, 16, 16, 16, __half, wmma::col_major> bf[2];
            #pragma unroll
            for (int i = 0; i < 4; i++)
                wmma::load_matrix_sync(af[i], sA[st] + (wm + i * 16) * HSTRIDE + kk, HSTRIDE);
            #pragma unroll
            for (int j = 0; j < 2; j++)
                wmma::load_matrix_sync(bf[j], sB[st] + (wn + j * 16) * HSTRIDE + kk, HSTRIDE);
            #pragma unroll
            for (int i = 0; i < 4; i++)
                #pragma unroll
                for (int j = 0; j < 2; j++)
                    wmma::mma_sync(acc[i][j], af[i], bf[j], acc[i][j]);
        }
    }

    if (MODE == 2 || MODE == 3) {
        // direct fragment -> global epilogue (no smem round trip)
        #pragma unroll
        for (int i = 0; i < 4; i++)
            #pragma unroll
            for (int j = 0; j < 2; j++) {
                float* cptr = Cf + (size_t)(bm + wm + i * 16) * ldc + bn + wn + j * 16;
                if (MODE == 2) {
                    wmma::fragment<wmma::accumulator, 16, 16, 16, float> e;
                    const float* eptr = extra + (size_t)(bm + wm + i * 16) * ldc + bn + wn + j * 16;
                    wmma::load_matrix_sync(e, eptr, ldc, wmma::mem_row_major);
                    #pragma unroll
                    for (int t = 0; t < 8; t++) acc[i][j].x[t] += e.x[t];
                }
                wmma::store_matrix_sync(cptr, acc[i][j], ldc, wmma::mem_row_major);
            }
    } else {
        __syncthreads();   // last tile's smem reads done before reuse as C stage
        // stage C tile through smem as float (65536 B <= 110592 B)
        float* csm = (float*)hsmem;
        #pragma unroll
        for (int i = 0; i < 4; i++)
            #pragma unroll
            for (int j = 0; j < 2; j++)
                wmma::store_matrix_sync(csm + (wm + i * 16) * 128 + wn + j * 16,
                                        acc[i][j], 128, wmma::mem_row_major);
        __syncthreads();

        #pragma unroll 4
        for (int i = tid; i < 128 * 128; i += 256) {
            int r = i >> 7, c = i & 127;
            float v = csm[i];
            int gm = bm + r, gn = bn + c;
            if (MODE == 4) Ch[(size_t)gm * ldc + gn] =
                __float2half(v * siluf(extra[(size_t)gm * ldc + gn]));
            if (MODE == 6) Cf[(size_t)gm * ldc + gn] = softplusf(v + extra[gn]);
        }
    }
}

// ================= chunked selective scan =================
// Partition: block = (seq, chunk). 4 warps, lane = p, warp owns 8 n-columns.
// h recurrence is linear diagonal: over a chunk, h_end = P ⊙ h_in + h_local.
#define PF 8

// phase 1: chunk-local h and P (chunks 0..NCHUNK-2; last chunk's state unused)
__global__ __launch_bounds__(128)
void scan_p1(const float* __restrict__ zx,
             const float* __restrict__ dtbuf,
             const float* __restrict__ A_log,
             float* __restrict__ hfin, float* __restrict__ Pbuf)
{
    int seq = blockIdx.x;          // 0..127
    int c   = blockIdx.y;          // 0..NCHUNK-2
    int t0  = c * CHUNK;
    int b = seq >> 6;
    int g = seq & 63;
    int w = threadIdx.x >> 5;
    int p = threadIdx.x & 31;
    int gkv = g >> 2;
    int nbase = w * 8;

    float An[8];
    #pragma unroll
    for (int j = 0; j < 8; j++)
        An[j] = -__expf(A_log[(size_t)(g * 32 + p) * DSTATE + nbase + j]);

    float h[8], Pr[8];
    #pragma unroll
    for (int j = 0; j < 8; j++) { h[j] = 0.f; Pr[j] = 1.f; }

    const float* dt_base = dtbuf + ((size_t)b * SEQLEN + t0) * DINNER + g * 32 + p;
    const float* x_base  = zx + ((size_t)b * SEQLEN + t0) * PROJ + OFF_X + gkv * 32 + p;
    const float* B_base  = zx + ((size_t)b * SEQLEN + t0) * PROJ + OFF_B + gkv * 32 + p;

    float pdt[PF], px[PF], pB[PF];
    #pragma unroll
    for (int i = 0; i < PF; i++) {
        pdt[i] = __ldg(dt_base + (size_t)i * DINNER);
        px[i]  = __ldg(x_base  + (size_t)i * PROJ);
        pB[i]  = __ldg(B_base  + (size_t)i * PROJ);
    }

    #pragma unroll 4
    for (int t = 0; t < CHUNK; t++) {
        int slot = t & (PF - 1);
        float dtv = pdt[slot], xv = px[slot], Ball = pB[slot];
        int tn = t + PF;
        if (tn < CHUNK) {
            pdt[slot] = __ldg(dt_base + (size_t)tn * DINNER);
            px[slot]  = __ldg(x_base  + (size_t)tn * PROJ);
            pB[slot]  = __ldg(B_base  + (size_t)tn * PROJ);
        }
        float dtx = dtv * xv;
        #pragma unroll
        for (int j = 0; j < 8; j++) {
            float Bv = __shfl_sync(FULLMASK, Ball, nbase + j);
            float dA = __expf(dtv * An[j]);
            h[j]  = dA * h[j] + dtx * Bv;
            Pr[j] = dA * Pr[j];
        }
    }

    size_t base = (((size_t)seq * NCHUNK + c) * 32 + p) * 32 + nbase;
    #pragma unroll
    for (int j = 0; j < 8; j++) {
        hfin[base + j] = h[j];
        Pbuf[base + j] = Pr[j];
    }
}

// fixup: hin[c] = P[c-1] * hin[c-1] + hfin[c-1]; hin[0] = 0
__global__ void scan_fix(const float* __restrict__ hfin,
                         const float* __restrict__ Pbuf,
                         float* __restrict__ hin)
{
    int id = blockIdx.x * 256 + threadIdx.x;       // 0 .. 128*1024
    int seq = id >> 10;
    int pn  = id & 1023;
    size_t base = (size_t)seq * NCHUNK * 1024 + pn;
    float hc = 0.f;
    hin[base] = 0.f;
    #pragma unroll
    for (int c = 1; c < NCHUNK; c++) {
        size_t prev = base + (size_t)(c - 1) * 1024;
        hc = Pbuf[prev] * hc + hfin[prev];
        hin[base + (size_t)c * 1024] = hc;
    }
}

// phase 2: full scan per chunk with correct h_in, emitting y partials
__global__ __launch_bounds__(128)
void scan_p2(const float* __restrict__ zx,
             const float* __restrict__ dtbuf,
             const float* __restrict__ A_log,
             const float* __restrict__ hin,
             float* __restrict__ ypart)
{
    int seq = blockIdx.x;          // 0..127
    int c   = blockIdx.y;          // 0..NCHUNK-1
    int t0  = c * CHUNK;
    int b = seq >> 6;
    int g = seq & 63;
    int w = threadIdx.x >> 5;
    int p = threadIdx.x & 31;
    int gkv = g >> 2;
    int nbase = w * 8;

    float An[8];
    #pragma unroll
    for (int j = 0; j < 8; j++)
        An[j] = -__expf(A_log[(size_t)(g * 32 + p) * DSTATE + nbase + j]);

    float h[8];
    {
        size_t base = (((size_t)seq * NCHUNK + c) * 32 + p) * 32 + nbase;
        #pragma unroll
        for (int j = 0; j < 8; j++) h[j] = hin[base + j];
    }

    const float* dt_base = dtbuf + ((size_t)b * SEQLEN + t0) * DINNER + g * 32 + p;
    const float* x_base  = zx + ((size_t)b * SEQLEN + t0) * PROJ + OFF_X + gkv * 32 + p;
    const float* B_base  = zx + ((size_t)b * SEQLEN + t0) * PROJ + OFF_B + gkv * 32 + p;
    const float* C_base  = zx + ((size_t)b * SEQLEN + t0) * PROJ + OFF_C + g * 32 + p;
    float* yp = ypart + ((size_t)seq * SEQLEN + t0) * 128 + w * 32 + p;

    float pdt[PF], px[PF], pB[PF], pC[PF];
    #pragma unroll
    for (int i = 0; i < PF; i++) {
        pdt[i] = __ldg(dt_base + (size_t)i * DINNER);
        px[i]  = __ldg(x_base  + (size_t)i * PROJ);
        pB[i]  = __ldg(B_base  + (size_t)i * PROJ);
        pC[i]  = __ldg(C_base  + (size_t)i * PROJ);
    }

    #pragma unroll 4
    for (int t = 0; t < CHUNK; t++) {
        int slot = t & (PF - 1);
        float dtv = pdt[slot], xv = px[slot], Ball = pB[slot], Call = pC[slot];
        int tn = t + PF;
        if (tn < CHUNK) {
            pdt[slot] = __ldg(dt_base + (size_t)tn * DINNER);
            px[slot]  = __ldg(x_base  + (size_t)tn * PROJ);
            pB[slot]  = __ldg(B_base  + (size_t)tn * PROJ);
            pC[slot]  = __ldg(C_base  + (size_t)tn * PROJ);
        }
        float dtx = dtv * xv;
        float acc = 0.f;
        #pragma unroll
        for (int j = 0; j < 8; j++) {
            float Bv = __shfl_sync(FULLMASK, Ball, nbase + j);
            float Cv = __shfl_sync(FULLMASK, Call, nbase + j);
            float dA = __expf(dtv * An[j]);
            h[j] = dA * h[j] + dtx * Bv;
            acc += h[j] * Cv;
        }
        yp[(size_t)t * 128] = acc;
    }
}

// ---------------- combine 4 partial y + skip D + silu(z) gate -> half ----------------
__global__ void combine_kernel(const float* __restrict__ ypart,
                               const float* __restrict__ zx,
                               const float* __restrict__ Dp,
                               __half* __restrict__ out)
{
    int idx = blockIdx.x * 256 + threadIdx.x;      // 0 .. NTOK*DINNER
    int tok = idx >> 11;
    int i   = idx & 2047;
    int b = tok >> 10, t = tok & 1023;
    int g = i >> 5, p = i & 31;
    int seq = b * 64 + g;
    int gkv = g >> 2;

    const float* yp = ypart + ((size_t)seq * SEQLEN + t) * 128 + p;
    float y = yp[0] + yp[32] + yp[64] + yp[96];

    float xv = zx[(size_t)tok * PROJ + OFF_X + gkv * 32 + p];
    float zv = zx[(size_t)tok * PROJ + OFF_Z + i];
    y += xv * Dp[i];
    float sig = 1.f / (1.f + __expf(-zv));
    out[(size_t)tok * DINNER + i] = __float2half(y * (zv * sig));
}

// ---------------- launch ----------------
static inline void halfw(const float* w, __half* dst, size_t n)
{
    int n4 = (int)(n / 4);
    halfw_kernel<<<(n4 + 255) / 256, 256>>>((const float4*)w, (__half2*)dst, n4);
}

extern "C" void kernel_launch(void* const* d_in, const int* in_sizes, int n_in,
                              void* d_out, int out_size)
{
    const float* hidden     = (const float*)d_in[0];
    const float* in_proj_w  = (const float*)d_in[1];
    const float* dt_proj_w  = (const float*)d_in[2];
    const float* dt_proj_b  = (const float*)d_in[3];
    const float* A_log      = (const float*)d_in[4];
    const float* D_param    = (const float*)d_in[5];
    const float* out_proj_w = (const float*)d_in[6];
    const float* gate_w     = (const float*)d_in[7];
    const float* up_w       = (const float*)d_in[8];
    const float* down_w     = (const float*)d_in[9];
    const float* norm1_w    = (const float*)d_in[10];
    const float* norm2_w    = (const float*)d_in[11];
    float* out = (float*)d_out;

    float *p_zx, *p_dt, *p_ypart, *p_hfin, *p_P, *p_hin, *p_h, *p_gate;
    __half *p_xn1h, *p_dtrawh, *p_ygh, *p_xn2h, *p_ffh;
    __half *p_win, *p_wdt, *p_wout, *p_wgate, *p_wup, *p_wdown;
    cudaGetSymbolAddress((void**)&p_zx,    g_zx);
    cudaGetSymbolAddress((void**)&p_dt,    g_dt);
    cudaGetSymbolAddress((void**)&p_ypart, g_ypart);
    cudaGetSymbolAddress((void**)&p_hfin,  g_hfin);
    cudaGetSymbolAddress((void**)&p_P,     g_P);
    cudaGetSymbolAddress((void**)&p_hin,   g_hin);
    cudaGetSymbolAddress((void**)&p_h,     g_h);
    cudaGetSymbolAddress((void**)&p_gate,  g_gate);
    cudaGetSymbolAddress((void**)&p_xn1h,  g_xn1h);
    cudaGetSymbolAddress((void**)&p_dtrawh,g_dtrawh);
    cudaGetSymbolAddress((void**)&p_ygh,   g_ygh);
    cudaGetSymbolAddress((void**)&p_xn2h,  g_xn2h);
    cudaGetSymbolAddress((void**)&p_ffh,   g_ffh);
    cudaGetSymbolAddress((void**)&p_win,   g_wh_in);
    cudaGetSymbolAddress((void**)&p_wdt,   g_wh_dt);
    cudaGetSymbolAddress((void**)&p_wout,  g_wh_out);
    cudaGetSymbolAddress((void**)&p_wgate, g_wh_gate);
    cudaGetSymbolAddress((void**)&p_wup,   g_wh_up);
    cudaGetSymbolAddress((void**)&p_wdown, g_wh_down);

    cudaFuncSetAttribute(gemm16<2>, cudaFuncAttributeMaxDynamicSharedMemorySize, GEMM_SMEM16);
    cudaFuncSetAttribute(gemm16<3>, cudaFuncAttributeMaxDynamicSharedMemorySize, GEMM_SMEM16);
    cudaFuncSetAttribute(gemm16<4>, cudaFuncAttributeMaxDynamicSharedMemorySize, GEMM_SMEM16);
    cudaFuncSetAttribute(gemm16<6>, cudaFuncAttributeMaxDynamicSharedMemorySize, GEMM_SMEM16);

    // 0) stage all weights to fp16 once
    halfw(in_proj_w,  p_win,   (size_t)PROJ * DMODEL);
    halfw(dt_proj_w,  p_wdt,   (size_t)DINNER * DTRANK);
    halfw(out_proj_w, p_wout,  (size_t)DMODEL * DINNER);
    halfw(gate_w,     p_wgate, (size_t)DFF * DMODEL);
    halfw(up_w,       p_wup,   (size_t)DFF * DMODEL);
    halfw(down_w,     p_wdown, (size_t)DMODEL * DFF);

    // 1) norm1 -> fp16
    rmsnorm_kernel<<<NTOK, 256>>>(hidden, norm1_w, p_xn1h);
    // 2) in_proj (fp16) -> zx fp32
    gemm16<3><<<dim3(PROJ / 128, NTOK / 128), 256, GEMM_SMEM16>>>(
        p_xn1h, DMODEL, p_win, DMODEL, p_zx, nullptr, PROJ, nullptr, DMODEL);
    // 2b) slice dt_raw columns -> fp16
    cvt_dtraw_kernel<<<(NTOK * DTRANK) / 256, 256>>>(p_zx, p_dtrawh);
    // 3) dt (fp16) = softplus(dt_raw @ dt_proj_w^T + b) -> fp32
    gemm16<6><<<dim3(DINNER / 128, NTOK / 128), 256, GEMM_SMEM16>>>(
        p_dtrawh, DTRANK, p_wdt, DTRANK, p_dt, nullptr, DINNER, dt_proj_b, DTRANK);
    // 4) chunked selective scan
    scan_p1<<<dim3(128, NCHUNK - 1), 128>>>(p_zx, p_dt, A_log, p_hfin, p_P);
    scan_fix<<<(128 * 1024) / 256, 256>>>(p_hfin, p_P, p_hin);
    scan_p2<<<dim3(128, NCHUNK), 128>>>(p_zx, p_dt, A_log, p_hin, p_ypart);
    // 5) combine -> ygh (fp16)
    combine_kernel<<<(NTOK * DINNER) / 256, 256>>>(p_ypart, p_zx, D_param, p_ygh);
    // 6) out_proj (fp16) + residual(hidden) -> h (fp32)
    gemm16<2><<<dim3(DMODEL / 128, NTOK / 128), 256, GEMM_SMEM16>>>(
        p_ygh, DINNER, p_wout, DINNER, p_h, nullptr, DMODEL, hidden, DINNER);
    // 7) norm2 -> xn2h (fp16)
    rmsnorm_kernel<<<NTOK, 256>>>(p_h, norm2_w, p_xn2h);
    // 8) gate GEMM (fp16) -> g_gate (fp32)
    gemm16<3><<<dim3(DFF / 128, NTOK / 128), 256, GEMM_SMEM16>>>(
        p_xn2h, DMODEL, p_wgate, DMODEL, p_gate, nullptr, DFF, nullptr, DMODEL);
    // 9) up GEMM (fp16) fused silu(gate)*up -> ffh (fp16)
    gemm16<4><<<dim3(DFF / 128, NTOK / 128), 256, GEMM_SMEM16>>>(
        p_xn2h, DMODEL, p_wup, DMODEL, nullptr, p_ffh, DFF, p_gate, DMODEL);
    // 10) down (fp16) + residual(h) -> out (fp32)
    gemm16<2><<<dim3(DMODEL / 128, NTOK / 128), 256, GEMM_SMEM16>>>(
        p_ffh, DFF, p_wdown, DFF, out, nullptr, DMODEL, p_h, DFF);
}